// round 10
// baseline (speedup 1.0000x reference)
#include <cuda_runtime.h>
#include <cuda_bf16.h>
#include <stdint.h>

#define NN 100000
#define NE 1600000
#define FD 128
#define NC 40

__device__ int   g_deg[NN];
__device__ int   g_start[NN];
__device__ int   g_cursor[NN];
__device__ float g_invdeg[NN];
__device__ int   g_csr[NE];
__device__ float g_hA[(size_t)NN * FD];
__device__ float g_hB[(size_t)NN * FD];
__device__ float g_agg[(size_t)NN * FD];
__device__ float g_tA[(size_t)NN * NC];
__device__ float g_t40[(size_t)NN * NC];
__device__ int   g_mask4;
__device__ int   g_blockSums[128];

__device__ __forceinline__ const float* pick_in(int sel, const float* p) {
    if (sel == 1) return g_hA;
    if (sel == 2) return g_hB;
    return p;
}
__device__ __forceinline__ float* pick_out(int sel, float* p) {
    if (sel == 1) return g_hA;
    if (sel == 2) return g_hB;
    if (sel == 3) return g_tA;
    return p;
}

__device__ __forceinline__ unsigned long long pack_dup(float a) {
    unsigned long long r;
    asm("mov.b64 %0, {%1, %1};" : "=l"(r) : "f"(a));
    return r;
}
__device__ __forceinline__ void ffma2(unsigned long long& d,
                                      unsigned long long a,
                                      unsigned long long b) {
    asm("fma.rn.f32x2 %0, %1, %2, %0;" : "+l"(d) : "l"(a), "l"(b));
}
__device__ __forceinline__ float2 unpack2(unsigned long long v) {
    float2 r;
    asm("mov.b64 {%0, %1}, %2;" : "=f"(r.x), "=f"(r.y) : "l"(v));
    return r;
}

template<int CM>
__device__ __forceinline__ int swz(int c) {
    return (c & ~CM) | ((c + (c >> 3)) & CM);
}

// ---------------- setup: zero deg + mask dtype probe ------------------------
__global__ void k_setup(const unsigned int* __restrict__ m) {
    int i = blockIdx.x * blockDim.x + threadIdx.x;
    if (i < NN) g_deg[i] = 0;
    if (blockIdx.x == 0 && threadIdx.x < 32) {
        int lane = threadIdx.x;
        unsigned bad = 0;
        for (int j = lane; j < 64; j += 32) {
            unsigned v = m[j];
            if (!(v == 0u || v == 1u || v == 0x3F800000u)) bad = 1;
        }
        unsigned any = __ballot_sync(0xFFFFFFFFu, bad);
        if (lane == 0) g_mask4 = (any == 0u) ? 1 : 0;
    }
}

__global__ void k_hist(const int* __restrict__ dst) {
    int i = blockIdx.x * blockDim.x + threadIdx.x;
    if (i < NE) atomicAdd(&g_deg[dst[i]], 1);
}

// ---------------- hierarchical exclusive scan -------------------------------
__global__ void __launch_bounds__(1024) k_scanA() {
    const int tid  = threadIdx.x;
    const int lane = tid & 31;
    const int wid  = tid >> 5;
    const int i    = blockIdx.x * 1024 + tid;

    int v = (i < NN) ? g_deg[i] : 0;
    int x = v;
    #pragma unroll
    for (int off = 1; off < 32; off <<= 1) {
        int y = __shfl_up_sync(0xFFFFFFFFu, x, off);
        if (lane >= off) x += y;
    }
    __shared__ int wsum[32];
    if (lane == 31) wsum[wid] = x;
    __syncthreads();
    if (wid == 0) {
        int w = wsum[lane];
        #pragma unroll
        for (int off = 1; off < 32; off <<= 1) {
            int y = __shfl_up_sync(0xFFFFFFFFu, w, off);
            if (lane >= off) w += y;
        }
        wsum[lane] = w;
    }
    __syncthreads();
    int base = (wid > 0) ? wsum[wid - 1] : 0;
    int incl = x + base;
    if (i < NN) g_start[i] = incl - v;
    if (tid == 1023) g_blockSums[blockIdx.x] = incl;
}

// each 256-block self-computes its superblock prefix, applies, inits extras
__global__ void k_scanC(int nblk) {
    const int t = threadIdx.x;
    const int B = (blockIdx.x * 256) >> 10;
    __shared__ int wsum[8];
    __shared__ int s_off;
    int v = (t < B) ? g_blockSums[t] : 0;
    #pragma unroll
    for (int off = 16; off > 0; off >>= 1)
        v += __shfl_down_sync(0xFFFFFFFFu, v, off);
    if ((t & 31) == 0) wsum[t >> 5] = v;
    __syncthreads();
    if (t == 0) {
        int s = 0;
        #pragma unroll
        for (int w = 0; w < 8; w++) s += wsum[w];
        s_off = s;
    }
    __syncthreads();
    int i = blockIdx.x * 256 + t;
    if (i < NN) {
        int st = g_start[i] + s_off;
        g_start[i]  = st;
        g_cursor[i] = st;
        int d = g_deg[i];
        g_invdeg[i] = 1.0f / (float)(d > 0 ? d : 1);
    }
}

__global__ void k_scatter(const int* __restrict__ src, const int* __restrict__ dst) {
    int i = blockIdx.x * blockDim.x + threadIdx.x;
    if (i < NE) {
        int d = dst[i];
        int p = atomicAdd(&g_cursor[d], 1);
        g_csr[p] = src[i];
    }
}

// ---------------- mean aggregation, 128-wide (warp per node) ----------------
__global__ void k_agg(int hsel, const float* __restrict__ hp) {
    const float* __restrict__ h = pick_in(hsel, hp);
    int gw   = (blockIdx.x * blockDim.x + threadIdx.x) >> 5;
    int lane = threadIdx.x & 31;
    if (gw >= NN) return;
    int s = g_start[gw];
    int d = g_deg[gw];
    float4 acc0 = make_float4(0.f, 0.f, 0.f, 0.f);
    float4 acc1 = make_float4(0.f, 0.f, 0.f, 0.f);
    int e = 0;
    for (; e + 1 < d; e += 2) {
        int s0 = g_csr[s + e];
        int s1 = g_csr[s + e + 1];
        float4 v0 = ((const float4*)(h + (size_t)s0 * FD))[lane];
        float4 v1 = ((const float4*)(h + (size_t)s1 * FD))[lane];
        acc0.x += v0.x; acc0.y += v0.y; acc0.z += v0.z; acc0.w += v0.w;
        acc1.x += v1.x; acc1.y += v1.y; acc1.z += v1.z; acc1.w += v1.w;
    }
    if (e < d) {
        int s0 = g_csr[s + e];
        float4 v0 = ((const float4*)(h + (size_t)s0 * FD))[lane];
        acc0.x += v0.x; acc0.y += v0.y; acc0.z += v0.z; acc0.w += v0.w;
    }
    float iv = g_invdeg[gw];
    float4 r;
    r.x = (acc0.x + acc1.x) * iv;
    r.y = (acc0.y + acc1.y) * iv;
    r.z = (acc0.z + acc1.z) * iv;
    r.w = (acc0.w + acc1.w) * iv;
    ((float4*)(g_agg + (size_t)gw * FD))[lane] = r;
}

// ---------------- mean aggregation, 40-wide (lanes 0-9 of each warp) --------
__global__ void k_agg40() {
    const float* __restrict__ t = g_tA;
    int gw   = (blockIdx.x * blockDim.x + threadIdx.x) >> 5;
    int lane = threadIdx.x & 31;
    if (gw >= NN) return;
    int s = g_start[gw];
    int d = g_deg[gw];
    float4 acc0 = make_float4(0.f, 0.f, 0.f, 0.f);
    float4 acc1 = make_float4(0.f, 0.f, 0.f, 0.f);
    const bool act = (lane < 10);
    int e = 0;
    for (; e + 1 < d; e += 2) {
        int s0 = g_csr[s + e];
        int s1 = g_csr[s + e + 1];
        if (act) {
            float4 v0 = *(const float4*)(t + (size_t)s0 * NC + lane * 4);
            float4 v1 = *(const float4*)(t + (size_t)s1 * NC + lane * 4);
            acc0.x += v0.x; acc0.y += v0.y; acc0.z += v0.z; acc0.w += v0.w;
            acc1.x += v1.x; acc1.y += v1.y; acc1.z += v1.z; acc1.w += v1.w;
        }
    }
    if (e < d && act) {
        int s0 = g_csr[s + e];
        float4 v0 = *(const float4*)(t + (size_t)s0 * NC + lane * 4);
        acc0.x += v0.x; acc0.y += v0.y; acc0.z += v0.z; acc0.w += v0.w;
    }
    if (act) {
        float iv = g_invdeg[gw];
        float4 r;
        r.x = (acc0.x + acc1.x) * iv;
        r.y = (acc0.y + acc1.y) * iv;
        r.z = (acc0.z + acc1.z) * iv;
        r.w = (acc0.w + acc1.w) * iv;
        *(float4*)(g_t40 + (size_t)gw * NC + lane * 4) = r;
    }
}

// ---------------- GEMM ------------------------------------------------------
// BM=128, BK=16. 256 thr: tx=tid%8 (N), ty=tid/8 (M), TM=4 rows/thread.
// KT=16: K=256 = [A0|A1]@[B0;B1].  KT=8: K=128, A0@B0.
// ADDM=1: vals += g_t40[r] (read via device symbol, NOT a host-passed ptr).
// ZBIAS=1: bias treated as zero (bias arg unused).
template<int BN, int TN, int KT, int EPI, int ADDM, int ZBIAS>
__global__ void __launch_bounds__(256)
k_gemm(int a0sel, const float* __restrict__ A0p,
       const float* __restrict__ B0, const float* __restrict__ B1,
       const float* __restrict__ bias,
       int osel, float* __restrict__ outp, int Nout,
       const void* __restrict__ maskp,
       const float* __restrict__ gh, const int* __restrict__ g2)
{
    constexpr int BM = 128, BK = 16, TM = 4;
    constexpr int TX  = 8;
    constexpr int TN2 = TN / 2;
    constexpr int NCH = TN / 4;
    constexpr int CM  = NCH - 1;
    constexpr int BLD = BK * BN / 256;
    static_assert(BN / TN == TX, "tile");

    const float* __restrict__ A0 = pick_in(a0sel, A0p);
    const float* __restrict__ A1 = g_agg;
    float* __restrict__ out = pick_out(osel, outp);

    __shared__ float As[BK][2 * BM];
    __shared__ float Bs[BK][BN];

    const int tid = threadIdx.x;
    const int tx  = tid % TX;
    const int ty  = tid / TX;
    const int row0 = blockIdx.x * BM;

    unsigned long long acc2[TM][TN2];
    #pragma unroll
    for (int i = 0; i < TM; i++)
        #pragma unroll
        for (int j = 0; j < TN2; j++) acc2[i][j] = 0ull;

    const int ar = tid >> 1;
    const int ak = (tid & 1) * 8;
    const int bk = (tid * BLD) / BN;
    const int bn = (tid * BLD) % BN;

    #pragma unroll 1
    for (int kb = 0; kb < KT; ++kb) {
        const float* __restrict__ A = (KT == 16 && kb >= 8) ? A1 : A0;
        const float* __restrict__ B = (KT == 16 && kb >= 8) ? B1 : B0;
        const int kBase = (kb * BK) & 127;

        float a[8];
        const int grow = row0 + ar;
        if (grow < NN) {
            const float* p = A + (size_t)grow * 128 + kBase + ak;
            *(float4*)&a[0] = *(const float4*)(p);
            *(float4*)&a[4] = *(const float4*)(p + 4);
        } else {
            #pragma unroll
            for (int j = 0; j < 8; j++) a[j] = 0.f;
        }
        float4 bv[BLD / 4];
        #pragma unroll
        for (int q = 0; q < BLD / 4; q++) {
            const int nn = bn + q * 4;
            if (nn < Nout)
                bv[q] = *(const float4*)(B + (size_t)(kBase + bk) * Nout + nn);
            else
                bv[q] = make_float4(0.f, 0.f, 0.f, 0.f);
        }

        __syncthreads();
        #pragma unroll
        for (int j = 0; j < 8; j++)
            ((unsigned long long*)&As[ak + j][0])[ar] = pack_dup(a[j]);
        #pragma unroll
        for (int q = 0; q < BLD / 4; q++) {
            int c = (bn >> 2) + q;
            *(float4*)&Bs[bk][swz<CM>(c) * 4] = bv[q];
        }
        __syncthreads();

        #pragma unroll
        for (int kk = 0; kk < BK; kk++) {
            unsigned long long ap[TM];
            {
                const ulonglong2* Ad = (const ulonglong2*)&As[kk][ty * 8];
                ulonglong2 t0 = Ad[0], t1 = Ad[1];
                ap[0] = t0.x; ap[1] = t0.y; ap[2] = t1.x; ap[3] = t1.y;
            }
            unsigned long long bp[TN2];
            #pragma unroll
            for (int q = 0; q < NCH; q++) {
                int c = tx * NCH + q;
                ulonglong2 v = *(const ulonglong2*)&Bs[kk][swz<CM>(c) * 4];
                bp[2 * q]     = v.x;
                bp[2 * q + 1] = v.y;
            }
            #pragma unroll
            for (int i = 0; i < TM; i++)
                #pragma unroll
                for (int j = 0; j < TN2; j++)
                    ffma2(acc2[i][j], ap[i], bp[j]);
        }
    }

    // ---- epilogue ----
    const int c0 = tx * TN;
    float bfr[TN];
    #pragma unroll
    for (int j = 0; j < TN; j++)
        bfr[j] = (!ZBIAS && c0 + j < Nout) ? bias[c0 + j] : 0.f;
    const int m4 = EPI ? g_mask4 : 0;

    #pragma unroll
    for (int i = 0; i < TM; i++) {
        const int r = row0 + ty * TM + i;
        if (r >= NN) continue;
        float vals[TN];
        #pragma unroll
        for (int j = 0; j < TN2; j++) {
            float2 v = unpack2(acc2[i][j]);
            vals[2 * j + 0] = v.x + bfr[2 * j + 0];
            vals[2 * j + 1] = v.y + bfr[2 * j + 1];
        }
        if (ADDM && c0 < Nout) {
            const float* am = g_t40 + (size_t)r * NC + c0;
            #pragma unroll
            for (int q = 0; q < TN / 4; q++) {
                if (c0 + q * 4 < Nout) {
                    float4 av = *(const float4*)(am + q * 4);
                    vals[q * 4 + 0] += av.x; vals[q * 4 + 1] += av.y;
                    vals[q * 4 + 2] += av.z; vals[q * 4 + 3] += av.w;
                }
            }
        }
        if (EPI) {
            bool mb = m4 ? (((const unsigned int*)maskp)[r] != 0u)
                         : (((const unsigned char*)maskp)[r] != 0);
            if (!mb) {
                const float* gr = gh + (size_t)g2[r] * 128 + c0;
                #pragma unroll
                for (int q = 0; q < TN / 4; q++) {
                    float4 gv = *(const float4*)(gr + q * 4);
                    vals[q * 4 + 0] = gv.x; vals[q * 4 + 1] = gv.y;
                    vals[q * 4 + 2] = gv.z; vals[q * 4 + 3] = gv.w;
                }
            }
            #pragma unroll
            for (int j = 0; j < TN; j++) vals[j] = fmaxf(vals[j], 0.f);
        }
        float* orow = out + (size_t)r * Nout + c0;
        if (c0 + TN <= Nout) {
            #pragma unroll
            for (int q = 0; q < TN / 4; q++)
                *(float4*)(orow + q * 4) = *(const float4*)&vals[q * 4];
        } else if (c0 < Nout) {
            for (int j = 0; j < TN && c0 + j < Nout; j++) orow[j] = vals[j];
        }
    }
}

// ---------------- launch ----------------------------------------------------
extern "C" void kernel_launch(void* const* d_in, const int* in_sizes, int n_in,
                              void* d_out, int out_size)
{
    const float* feat = (const float*)d_in[0];
    const float* gh   = (const float*)d_in[1];
    const float* gh2  = (const float*)d_in[2];
    const float* W1s  = (const float*)d_in[3];
    const float* W1n  = (const float*)d_in[4];
    const float* b1   = (const float*)d_in[5];
    const float* W2s  = (const float*)d_in[6];
    const float* W2n  = (const float*)d_in[7];
    const float* b2   = (const float*)d_in[8];
    const float* W3s  = (const float*)d_in[9];
    const float* W3n  = (const float*)d_in[10];
    const float* b3   = (const float*)d_in[11];
    const int*   esrc = (const int*)d_in[12];
    const int*   edst = (const int*)d_in[13];
    const int*   g2   = (const int*)d_in[14];
    const void*  mask = (const void*)d_in[15];
    float* out = (float*)d_out;

    const int TB = 256;
    const int scanBlocks = (NN + 1023) / 1024;

    k_setup<<<(NN + TB - 1) / TB, TB>>>((const unsigned int*)mask);
    k_hist<<<(NE + TB - 1) / TB, TB>>>(edst);
    k_scanA<<<scanBlocks, 1024>>>();
    k_scanC<<<(NN + TB - 1) / TB, TB>>>(scanBlocks);
    k_scatter<<<(NE + TB - 1) / TB, TB>>>(esrc, edst);

    const int aggBlocks  = (NN * 32 + TB - 1) / TB;
    const int gemmBlocks = (NN + 127) / 128;

    // Layer 1
    k_agg<<<aggBlocks, TB>>>(0, feat);
    k_gemm<128, 16, 16, 1, 0, 0><<<gemmBlocks, TB>>>(0, feat, W1s, W1n, b1,
            1, nullptr, 128, mask, gh, g2);
    // Layer 2
    k_agg<<<aggBlocks, TB>>>(1, nullptr);
    k_gemm<128, 16, 16, 1, 0, 0><<<gemmBlocks, TB>>>(1, nullptr, W2s, W2n, b2,
            2, nullptr, 128, mask, gh2, g2);
    // Layer 3 transform-first: t = hB @ W3n (zero bias) -> g_tA; agg40;
    // out = hB @ W3s + g_t40 + b3
    k_gemm<64, 8, 8, 0, 0, 1><<<gemmBlocks, TB>>>(2, nullptr, W3n, nullptr, nullptr,
            3, nullptr, NC, nullptr, nullptr, nullptr);
    k_agg40<<<aggBlocks, TB>>>();
    k_gemm<64, 8, 8, 0, 1, 0><<<gemmBlocks, TB>>>(2, nullptr, W3s, nullptr, b3,
            0, out, NC, nullptr, nullptr, nullptr);
}

// round 11
// speedup vs baseline: 1.0918x; 1.0918x over previous
#include <cuda_runtime.h>
#include <cuda_bf16.h>
#include <stdint.h>

#define NN 100000
#define NE 1600000
#define FD 128
#define NC 40

__device__ int   g_deg[NN];
__device__ int   g_start[NN];
__device__ int   g_cursor[NN];
__device__ float g_invdeg[NN];
__device__ int   g_csr[NE];
__device__ float g_hA[(size_t)NN * FD];
__device__ float g_hB[(size_t)NN * FD];
__device__ float g_agg[(size_t)NN * FD];
__device__ float g_tA[(size_t)NN * NC];
__device__ float g_t40[(size_t)NN * NC];
__device__ int   g_mask4;
__device__ int   g_blockSums[128];

__device__ __forceinline__ const float* pick_in(int sel, const float* p) {
    if (sel == 1) return g_hA;
    if (sel == 2) return g_hB;
    return p;
}
__device__ __forceinline__ float* pick_out(int sel, float* p) {
    if (sel == 1) return g_hA;
    if (sel == 2) return g_hB;
    if (sel == 3) return g_tA;
    return p;
}

__device__ __forceinline__ unsigned long long pack_dup(float a) {
    unsigned long long r;
    asm("mov.b64 %0, {%1, %1};" : "=l"(r) : "f"(a));
    return r;
}
__device__ __forceinline__ void ffma2(unsigned long long& d,
                                      unsigned long long a,
                                      unsigned long long b) {
    asm("fma.rn.f32x2 %0, %1, %2, %0;" : "+l"(d) : "l"(a), "l"(b));
}
__device__ __forceinline__ float2 unpack2(unsigned long long v) {
    float2 r;
    asm("mov.b64 {%0, %1}, %2;" : "=f"(r.x), "=f"(r.y) : "l"(v));
    return r;
}

// ---------------- setup: zero deg + mask dtype probe ------------------------
__global__ void k_setup(const unsigned int* __restrict__ m) {
    int i = blockIdx.x * blockDim.x + threadIdx.x;
    if (i < NN) g_deg[i] = 0;
    if (blockIdx.x == 0 && threadIdx.x < 32) {
        int lane = threadIdx.x;
        unsigned bad = 0;
        for (int j = lane; j < 64; j += 32) {
            unsigned v = m[j];
            if (!(v == 0u || v == 1u || v == 0x3F800000u)) bad = 1;
        }
        unsigned any = __ballot_sync(0xFFFFFFFFu, bad);
        if (lane == 0) g_mask4 = (any == 0u) ? 1 : 0;
    }
}

__global__ void k_hist(const int* __restrict__ dst) {
    int i = blockIdx.x * blockDim.x + threadIdx.x;
    if (i < NE) atomicAdd(&g_deg[dst[i]], 1);
}

// ---------------- hierarchical exclusive scan -------------------------------
__global__ void __launch_bounds__(1024) k_scanA() {
    const int tid  = threadIdx.x;
    const int lane = tid & 31;
    const int wid  = tid >> 5;
    const int i    = blockIdx.x * 1024 + tid;

    int v = (i < NN) ? g_deg[i] : 0;
    int x = v;
    #pragma unroll
    for (int off = 1; off < 32; off <<= 1) {
        int y = __shfl_up_sync(0xFFFFFFFFu, x, off);
        if (lane >= off) x += y;
    }
    __shared__ int wsum[32];
    if (lane == 31) wsum[wid] = x;
    __syncthreads();
    if (wid == 0) {
        int w = wsum[lane];
        #pragma unroll
        for (int off = 1; off < 32; off <<= 1) {
            int y = __shfl_up_sync(0xFFFFFFFFu, w, off);
            if (lane >= off) w += y;
        }
        wsum[lane] = w;
    }
    __syncthreads();
    int base = (wid > 0) ? wsum[wid - 1] : 0;
    int incl = x + base;
    if (i < NN) g_start[i] = incl - v;
    if (tid == 1023) g_blockSums[blockIdx.x] = incl;
}

__global__ void k_scanC(int nblk) {
    const int t = threadIdx.x;
    const int B = (blockIdx.x * 256) >> 10;
    __shared__ int wsum[8];
    __shared__ int s_off;
    int v = (t < B) ? g_blockSums[t] : 0;
    #pragma unroll
    for (int off = 16; off > 0; off >>= 1)
        v += __shfl_down_sync(0xFFFFFFFFu, v, off);
    if ((t & 31) == 0) wsum[t >> 5] = v;
    __syncthreads();
    if (t == 0) {
        int s = 0;
        #pragma unroll
        for (int w = 0; w < 8; w++) s += wsum[w];
        s_off = s;
    }
    __syncthreads();
    int i = blockIdx.x * 256 + t;
    if (i < NN) {
        int st = g_start[i] + s_off;
        g_start[i]  = st;
        g_cursor[i] = st;
        int d = g_deg[i];
        g_invdeg[i] = 1.0f / (float)(d > 0 ? d : 1);
    }
}

__global__ void k_scatter(const int* __restrict__ src, const int* __restrict__ dst) {
    int i = blockIdx.x * blockDim.x + threadIdx.x;
    if (i < NE) {
        int d = dst[i];
        int p = atomicAdd(&g_cursor[d], 1);
        g_csr[p] = src[i];
    }
}

// ---------------- mean aggregation, 128-wide (warp per node) ----------------
__global__ void k_agg(int hsel, const float* __restrict__ hp) {
    const float* __restrict__ h = pick_in(hsel, hp);
    int gw   = (blockIdx.x * blockDim.x + threadIdx.x) >> 5;
    int lane = threadIdx.x & 31;
    if (gw >= NN) return;
    int s = g_start[gw];
    int d = g_deg[gw];
    float4 acc0 = make_float4(0.f, 0.f, 0.f, 0.f);
    float4 acc1 = make_float4(0.f, 0.f, 0.f, 0.f);
    int e = 0;
    for (; e + 1 < d; e += 2) {
        int s0 = g_csr[s + e];
        int s1 = g_csr[s + e + 1];
        float4 v0 = ((const float4*)(h + (size_t)s0 * FD))[lane];
        float4 v1 = ((const float4*)(h + (size_t)s1 * FD))[lane];
        acc0.x += v0.x; acc0.y += v0.y; acc0.z += v0.z; acc0.w += v0.w;
        acc1.x += v1.x; acc1.y += v1.y; acc1.z += v1.z; acc1.w += v1.w;
    }
    if (e < d) {
        int s0 = g_csr[s + e];
        float4 v0 = ((const float4*)(h + (size_t)s0 * FD))[lane];
        acc0.x += v0.x; acc0.y += v0.y; acc0.z += v0.z; acc0.w += v0.w;
    }
    float iv = g_invdeg[gw];
    float4 r;
    r.x = (acc0.x + acc1.x) * iv;
    r.y = (acc0.y + acc1.y) * iv;
    r.z = (acc0.z + acc1.z) * iv;
    r.w = (acc0.w + acc1.w) * iv;
    ((float4*)(g_agg + (size_t)gw * FD))[lane] = r;
}

// ---------------- mean aggregation, 40-wide (lanes 0-9 of each warp) --------
__global__ void k_agg40() {
    const float* __restrict__ t = g_tA;
    int gw   = (blockIdx.x * blockDim.x + threadIdx.x) >> 5;
    int lane = threadIdx.x & 31;
    if (gw >= NN) return;
    int s = g_start[gw];
    int d = g_deg[gw];
    float4 acc0 = make_float4(0.f, 0.f, 0.f, 0.f);
    float4 acc1 = make_float4(0.f, 0.f, 0.f, 0.f);
    const bool act = (lane < 10);
    int e = 0;
    for (; e + 1 < d; e += 2) {
        int s0 = g_csr[s + e];
        int s1 = g_csr[s + e + 1];
        if (act) {
            float4 v0 = *(const float4*)(t + (size_t)s0 * NC + lane * 4);
            float4 v1 = *(const float4*)(t + (size_t)s1 * NC + lane * 4);
            acc0.x += v0.x; acc0.y += v0.y; acc0.z += v0.z; acc0.w += v0.w;
            acc1.x += v1.x; acc1.y += v1.y; acc1.z += v1.z; acc1.w += v1.w;
        }
    }
    if (e < d && act) {
        int s0 = g_csr[s + e];
        float4 v0 = *(const float4*)(t + (size_t)s0 * NC + lane * 4);
        acc0.x += v0.x; acc0.y += v0.y; acc0.z += v0.z; acc0.w += v0.w;
    }
    if (act) {
        float iv = g_invdeg[gw];
        float4 r;
        r.x = (acc0.x + acc1.x) * iv;
        r.y = (acc0.y + acc1.y) * iv;
        r.z = (acc0.z + acc1.z) * iv;
        r.w = (acc0.w + acc1.w) * iv;
        *(float4*)(g_t40 + (size_t)gw * NC + lane * 4) = r;
    }
}

// ---------------- GEMM (R8-measured mainloop, extended epilogue) ------------
// BM=128, BK=16, TM=8, TX=BN/TN threads along N (=16).
// KT=16: K=256 = [A0|A1]@[B0;B1].  KT=8: K=128, A0@B0.
// EPI=1: out = relu(mask ? v : gh[g2[r]]).
// ADDM=1: v += g_t40[r] (device symbol).  ZBIAS=1: bias = 0.
template<int BN, int TN, int KT, int EPI, int ADDM, int ZBIAS>
__global__ void __launch_bounds__(256)
k_gemm(int a0sel, const float* __restrict__ A0p,
       const float* __restrict__ B0, const float* __restrict__ B1,
       const float* __restrict__ bias,
       int osel, float* __restrict__ outp, int Nout,
       const void* __restrict__ maskp,
       const float* __restrict__ gh, const int* __restrict__ g2)
{
    constexpr int BM = 128, BK = 16, TM = 8;
    constexpr int TX = BN / TN;                 // 16
    constexpr int BLD = BK * BN / 256;          // floats per thread for B tile
    constexpr int TN2 = TN / 2;

    const float* __restrict__ A0 = pick_in(a0sel, A0p);
    const float* __restrict__ A1 = g_agg;
    float* __restrict__ out = pick_out(osel, outp);

    __shared__ float As[BK][BM];
    __shared__ float Bs[BK][BN];

    const int tid = threadIdx.x;
    const int tx  = tid % TX;
    const int ty  = tid / TX;
    const int row0 = blockIdx.x * BM;

    unsigned long long acc2[TM][TN2];
    #pragma unroll
    for (int i = 0; i < TM; i++)
        #pragma unroll
        for (int j = 0; j < TN2; j++) acc2[i][j] = 0ull;

    const int ar = tid >> 1;            // 0..127
    const int ak = (tid & 1) * 8;       // 0 or 8
    const int bk = (tid * BLD) / BN;    // 0..15
    const int bn = (tid * BLD) % BN;

    #pragma unroll 1
    for (int kb = 0; kb < KT; ++kb) {
        const float* __restrict__ A = (KT == 16 && kb >= 8) ? A1 : A0;
        const float* __restrict__ B = (KT == 16 && kb >= 8) ? B1 : B0;
        const int kBase = (kb * BK) & 127;

        float4 a0, a1;
        const int grow = row0 + ar;
        if (grow < NN) {
            const float* p = A + (size_t)grow * 128 + kBase + ak;
            a0 = *(const float4*)(p);
            a1 = *(const float4*)(p + 4);
        } else {
            a0 = make_float4(0.f, 0.f, 0.f, 0.f);
            a1 = a0;
        }
        float4 bv[BLD / 4];
        #pragma unroll
        for (int q = 0; q < BLD / 4; q++) {
            const int nn = bn + q * 4;
            if (nn < Nout)
                bv[q] = *(const float4*)(B + (size_t)(kBase + bk) * Nout + nn);
            else
                bv[q] = make_float4(0.f, 0.f, 0.f, 0.f);
        }

        __syncthreads();
        As[ak + 0][ar] = a0.x; As[ak + 1][ar] = a0.y;
        As[ak + 2][ar] = a0.z; As[ak + 3][ar] = a0.w;
        As[ak + 4][ar] = a1.x; As[ak + 5][ar] = a1.y;
        As[ak + 6][ar] = a1.z; As[ak + 7][ar] = a1.w;
        #pragma unroll
        for (int q = 0; q < BLD / 4; q++)
            *(float4*)&Bs[bk][bn + q * 4] = bv[q];
        __syncthreads();

        #pragma unroll
        for (int kk = 0; kk < BK; kk++) {
            float af[TM];
            *(float4*)&af[0] = *(const float4*)&As[kk][ty * TM];
            *(float4*)&af[4] = *(const float4*)&As[kk][ty * TM + 4];
            unsigned long long bp[TN2];
            #pragma unroll
            for (int q = 0; q < TN2; q++)
                bp[q] = *(const unsigned long long*)&Bs[kk][tx * TN + 2 * q];
            #pragma unroll
            for (int i = 0; i < TM; i++) {
                unsigned long long ap = pack_dup(af[i]);
                #pragma unroll
                for (int j = 0; j < TN2; j++)
                    ffma2(acc2[i][j], ap, bp[j]);
            }
        }
    }

    // ---- epilogue ----
    const int c0 = tx * TN;
    float bfr[TN];
    #pragma unroll
    for (int j = 0; j < TN; j++)
        bfr[j] = (!ZBIAS && c0 + j < Nout) ? bias[c0 + j] : 0.f;
    const int m4 = EPI ? g_mask4 : 0;

    #pragma unroll
    for (int i = 0; i < TM; i++) {
        const int r = row0 + ty * TM + i;
        if (r >= NN) continue;
        float vals[TN];
        #pragma unroll
        for (int j = 0; j < TN2; j++) {
            float2 v = unpack2(acc2[i][j]);
            vals[2 * j + 0] = v.x + bfr[2 * j + 0];
            vals[2 * j + 1] = v.y + bfr[2 * j + 1];
        }
        if (ADDM && c0 < Nout) {
            const float* am = g_t40 + (size_t)r * NC + c0;
            #pragma unroll
            for (int q = 0; q < TN / 4; q++) {
                if (c0 + q * 4 < Nout) {
                    float4 av = *(const float4*)(am + q * 4);
                    vals[q * 4 + 0] += av.x; vals[q * 4 + 1] += av.y;
                    vals[q * 4 + 2] += av.z; vals[q * 4 + 3] += av.w;
                }
            }
        }
        if (EPI) {
            bool mb = m4 ? (((const unsigned int*)maskp)[r] != 0u)
                         : (((const unsigned char*)maskp)[r] != 0);
            if (!mb) {
                const float* gr = gh + (size_t)g2[r] * 128 + c0;
                #pragma unroll
                for (int q = 0; q < TN / 4; q++) {
                    float4 gv = *(const float4*)(gr + q * 4);
                    vals[q * 4 + 0] = gv.x; vals[q * 4 + 1] = gv.y;
                    vals[q * 4 + 2] = gv.z; vals[q * 4 + 3] = gv.w;
                }
            }
            #pragma unroll
            for (int j = 0; j < TN; j++) vals[j] = fmaxf(vals[j], 0.f);
        }
        float* orow = out + (size_t)r * Nout + c0;
        if (c0 + TN <= Nout) {
            #pragma unroll
            for (int q = 0; q < TN / 4; q++)
                *(float4*)(orow + q * 4) = *(const float4*)&vals[q * 4];
        } else if (c0 < Nout) {
            for (int j = 0; j < TN && c0 + j < Nout; j++) orow[j] = vals[j];
        }
    }
}

// ---------------- launch ----------------------------------------------------
extern "C" void kernel_launch(void* const* d_in, const int* in_sizes, int n_in,
                              void* d_out, int out_size)
{
    const float* feat = (const float*)d_in[0];
    const float* gh   = (const float*)d_in[1];
    const float* gh2  = (const float*)d_in[2];
    const float* W1s  = (const float*)d_in[3];
    const float* W1n  = (const float*)d_in[4];
    const float* b1   = (const float*)d_in[5];
    const float* W2s  = (const float*)d_in[6];
    const float* W2n  = (const float*)d_in[7];
    const float* b2   = (const float*)d_in[8];
    const float* W3s  = (const float*)d_in[9];
    const float* W3n  = (const float*)d_in[10];
    const float* b3   = (const float*)d_in[11];
    const int*   esrc = (const int*)d_in[12];
    const int*   edst = (const int*)d_in[13];
    const int*   g2   = (const int*)d_in[14];
    const void*  mask = (const void*)d_in[15];
    float* out = (float*)d_out;

    const int TB = 256;
    const int scanBlocks = (NN + 1023) / 1024;

    k_setup<<<(NN + TB - 1) / TB, TB>>>((const unsigned int*)mask);
    k_hist<<<(NE + TB - 1) / TB, TB>>>(edst);
    k_scanA<<<scanBlocks, 1024>>>();
    k_scanC<<<(NN + TB - 1) / TB, TB>>>(scanBlocks);
    k_scatter<<<(NE + TB - 1) / TB, TB>>>(esrc, edst);

    const int aggBlocks  = (NN * 32 + TB - 1) / TB;
    const int gemmBlocks = (NN + 127) / 128;

    // Layer 1
    k_agg<<<aggBlocks, TB>>>(0, feat);
    k_gemm<128, 8, 16, 1, 0, 0><<<gemmBlocks, TB>>>(0, feat, W1s, W1n, b1,
            1, nullptr, 128, mask, gh, g2);
    // Layer 2
    k_agg<<<aggBlocks, TB>>>(1, nullptr);
    k_gemm<128, 8, 16, 1, 0, 0><<<gemmBlocks, TB>>>(1, nullptr, W2s, W2n, b2,
            2, nullptr, 128, mask, gh2, g2);
    // Layer 3 transform-first: t = hB @ W3n -> g_tA; agg40;
    // out = hB @ W3s + g_t40 + b3
    k_gemm<64, 4, 8, 0, 0, 1><<<gemmBlocks, TB>>>(2, nullptr, W3n, nullptr, nullptr,
            3, nullptr, NC, nullptr, nullptr, nullptr);
    k_agg40<<<aggBlocks, TB>>>();
    k_gemm<64, 4, 8, 0, 1, 0><<<gemmBlocks, TB>>>(2, nullptr, W3s, nullptr, b3,
            0, out, NC, nullptr, nullptr, nullptr);
}

// round 13
// speedup vs baseline: 1.4678x; 1.3444x over previous
#include <cuda_runtime.h>
#include <cuda_bf16.h>
#include <stdint.h>

#define NN 100000
#define NE 1600000
#define FD 128
#define NC 40

__device__ int   g_deg[NN];
__device__ int   g_start[NN];
__device__ int   g_cursor[NN];
__device__ float g_invdeg[NN];
__device__ int   g_csr[NE];
__device__ float g_hA[(size_t)NN * FD];
__device__ float g_hB[(size_t)NN * FD];
__device__ float g_agg[(size_t)NN * FD];
__device__ float g_tA[(size_t)NN * NC];
__device__ float g_t40[(size_t)NN * NC];
__device__ int   g_mask4;
__device__ int   g_blockSums[128];

__device__ __forceinline__ const float* pick_in(int sel, const float* p) {
    if (sel == 1) return g_hA;
    if (sel == 2) return g_hB;
    return p;
}
__device__ __forceinline__ float* pick_out(int sel, float* p) {
    if (sel == 1) return g_hA;
    if (sel == 2) return g_hB;
    if (sel == 3) return g_tA;
    return p;
}

__device__ __forceinline__ unsigned long long pack_dup(float a) {
    unsigned long long r;
    asm("mov.b64 %0, {%1, %1};" : "=l"(r) : "f"(a));
    return r;
}
__device__ __forceinline__ void ffma2(unsigned long long& d,
                                      unsigned long long a,
                                      unsigned long long b) {
    asm("fma.rn.f32x2 %0, %1, %2, %0;" : "+l"(d) : "l"(a), "l"(b));
}
__device__ __forceinline__ float2 unpack2(unsigned long long v) {
    float2 r;
    asm("mov.b64 {%0, %1}, %2;" : "=f"(r.x), "=f"(r.y) : "l"(v));
    return r;
}
__device__ __forceinline__ uint32_t f2tf(float f) {
    uint32_t r;
    asm("cvt.rna.tf32.f32 %0, %1;" : "=r"(r) : "f"(f));
    return r;
}
__device__ __forceinline__ void mma_tf32(float* c,
                                         uint32_t a0, uint32_t a1,
                                         uint32_t a2, uint32_t a3,
                                         uint32_t b0, uint32_t b1) {
    asm("mma.sync.aligned.m16n8k8.row.col.f32.tf32.tf32.f32 "
        "{%0,%1,%2,%3}, {%4,%5,%6,%7}, {%8,%9}, {%0,%1,%2,%3};"
        : "+f"(c[0]), "+f"(c[1]), "+f"(c[2]), "+f"(c[3])
        : "r"(a0), "r"(a1), "r"(a2), "r"(a3), "r"(b0), "r"(b1));
}

// ---------------- setup: zero deg + mask dtype probe ------------------------
__global__ void k_setup(const unsigned int* __restrict__ m) {
    int i = blockIdx.x * blockDim.x + threadIdx.x;
    if (i < NN) g_deg[i] = 0;
    if (blockIdx.x == 0 && threadIdx.x < 32) {
        int lane = threadIdx.x;
        unsigned bad = 0;
        for (int j = lane; j < 64; j += 32) {
            unsigned v = m[j];
            if (!(v == 0u || v == 1u || v == 0x3F800000u)) bad = 1;
        }
        unsigned any = __ballot_sync(0xFFFFFFFFu, bad);
        if (lane == 0) g_mask4 = (any == 0u) ? 1 : 0;
    }
}

__global__ void k_hist(const int* __restrict__ dst) {
    int i = blockIdx.x * blockDim.x + threadIdx.x;
    if (i < NE) atomicAdd(&g_deg[dst[i]], 1);
}

// ---------------- hierarchical exclusive scan -------------------------------
__global__ void __launch_bounds__(1024) k_scanA() {
    const int tid  = threadIdx.x;
    const int lane = tid & 31;
    const int wid  = tid >> 5;
    const int i    = blockIdx.x * 1024 + tid;

    int v = (i < NN) ? g_deg[i] : 0;
    int x = v;
    #pragma unroll
    for (int off = 1; off < 32; off <<= 1) {
        int y = __shfl_up_sync(0xFFFFFFFFu, x, off);
        if (lane >= off) x += y;
    }
    __shared__ int wsum[32];
    if (lane == 31) wsum[wid] = x;
    __syncthreads();
    if (wid == 0) {
        int w = wsum[lane];
        #pragma unroll
        for (int off = 1; off < 32; off <<= 1) {
            int y = __shfl_up_sync(0xFFFFFFFFu, w, off);
            if (lane >= off) w += y;
        }
        wsum[lane] = w;
    }
    __syncthreads();
    int base = (wid > 0) ? wsum[wid - 1] : 0;
    int incl = x + base;
    if (i < NN) g_start[i] = incl - v;
    if (tid == 1023) g_blockSums[blockIdx.x] = incl;
}

__global__ void k_scanC(int nblk) {
    const int t = threadIdx.x;
    const int B = (blockIdx.x * 256) >> 10;
    __shared__ int wsum[8];
    __shared__ int s_off;
    int v = (t < B) ? g_blockSums[t] : 0;
    #pragma unroll
    for (int off = 16; off > 0; off >>= 1)
        v += __shfl_down_sync(0xFFFFFFFFu, v, off);
    if ((t & 31) == 0) wsum[t >> 5] = v;
    __syncthreads();
    if (t == 0) {
        int s = 0;
        #pragma unroll
        for (int w = 0; w < 8; w++) s += wsum[w];
        s_off = s;
    }
    __syncthreads();
    int i = blockIdx.x * 256 + t;
    if (i < NN) {
        int st = g_start[i] + s_off;
        g_start[i]  = st;
        g_cursor[i] = st;
        int d = g_deg[i];
        g_invdeg[i] = 1.0f / (float)(d > 0 ? d : 1);
    }
}

__global__ void k_scatter(const int* __restrict__ src, const int* __restrict__ dst) {
    int i = blockIdx.x * blockDim.x + threadIdx.x;
    if (i < NE) {
        int d = dst[i];
        int p = atomicAdd(&g_cursor[d], 1);
        g_csr[p] = src[i];
    }
}

// ---------------- mean aggregation, 128-wide (warp per node) ----------------
__global__ void k_agg(int hsel, const float* __restrict__ hp) {
    const float* __restrict__ h = pick_in(hsel, hp);
    int gw   = (blockIdx.x * blockDim.x + threadIdx.x) >> 5;
    int lane = threadIdx.x & 31;
    if (gw >= NN) return;
    int s = g_start[gw];
    int d = g_deg[gw];
    float4 acc0 = make_float4(0.f, 0.f, 0.f, 0.f);
    float4 acc1 = make_float4(0.f, 0.f, 0.f, 0.f);
    int e = 0;
    for (; e + 1 < d; e += 2) {
        int s0 = g_csr[s + e];
        int s1 = g_csr[s + e + 1];
        float4 v0 = ((const float4*)(h + (size_t)s0 * FD))[lane];
        float4 v1 = ((const float4*)(h + (size_t)s1 * FD))[lane];
        acc0.x += v0.x; acc0.y += v0.y; acc0.z += v0.z; acc0.w += v0.w;
        acc1.x += v1.x; acc1.y += v1.y; acc1.z += v1.z; acc1.w += v1.w;
    }
    if (e < d) {
        int s0 = g_csr[s + e];
        float4 v0 = ((const float4*)(h + (size_t)s0 * FD))[lane];
        acc0.x += v0.x; acc0.y += v0.y; acc0.z += v0.z; acc0.w += v0.w;
    }
    float iv = g_invdeg[gw];
    float4 r;
    r.x = (acc0.x + acc1.x) * iv;
    r.y = (acc0.y + acc1.y) * iv;
    r.z = (acc0.z + acc1.z) * iv;
    r.w = (acc0.w + acc1.w) * iv;
    ((float4*)(g_agg + (size_t)gw * FD))[lane] = r;
}

// ---------------- mean aggregation, 40-wide (lanes 0-9 of each warp) --------
__global__ void k_agg40() {
    const float* __restrict__ t = g_tA;
    int gw   = (blockIdx.x * blockDim.x + threadIdx.x) >> 5;
    int lane = threadIdx.x & 31;
    if (gw >= NN) return;
    int s = g_start[gw];
    int d = g_deg[gw];
    float4 acc0 = make_float4(0.f, 0.f, 0.f, 0.f);
    float4 acc1 = make_float4(0.f, 0.f, 0.f, 0.f);
    const bool act = (lane < 10);
    int e = 0;
    for (; e + 1 < d; e += 2) {
        int s0 = g_csr[s + e];
        int s1 = g_csr[s + e + 1];
        if (act) {
            float4 v0 = *(const float4*)(t + (size_t)s0 * NC + lane * 4);
            float4 v1 = *(const float4*)(t + (size_t)s1 * NC + lane * 4);
            acc0.x += v0.x; acc0.y += v0.y; acc0.z += v0.z; acc0.w += v0.w;
            acc1.x += v1.x; acc1.y += v1.y; acc1.z += v1.z; acc1.w += v1.w;
        }
    }
    if (e < d && act) {
        int s0 = g_csr[s + e];
        float4 v0 = *(const float4*)(t + (size_t)s0 * NC + lane * 4);
        acc0.x += v0.x; acc0.y += v0.y; acc0.z += v0.z; acc0.w += v0.w;
    }
    if (act) {
        float iv = g_invdeg[gw];
        float4 r;
        r.x = (acc0.x + acc1.x) * iv;
        r.y = (acc0.y + acc1.y) * iv;
        r.z = (acc0.z + acc1.z) * iv;
        r.w = (acc0.w + acc1.w) * iv;
        *(float4*)(g_t40 + (size_t)gw * NC + lane * 4) = r;
    }
}

// ---------------- TF32 tensor-core GEMM (layers 1 & 2) ----------------------
// out = relu( mask ? ([h|agg] @ [Bself;Bneigh] + bias) : gh[g2] )
// BM=128, BN=128, K=256 (16 kb-steps of BK=16). 8 warps; warp w owns rows
// 16w..16w+15 x all 128 cols = 16 m16n8 tiles. SMEM: A [128][20] (stride 20 ->
// conflict-free frag loads), B [16][136] (stride 136 -> conflict-free).
__global__ void __launch_bounds__(256)
k_gemm_tc(int a0sel, const float* __restrict__ A0p,
          const float* __restrict__ B0, const float* __restrict__ B1,
          const float* __restrict__ bias,
          int osel,
          const void* __restrict__ maskp,
          const float* __restrict__ gh, const int* __restrict__ g2)
{
    const float* __restrict__ A0 = pick_in(a0sel, A0p);
    const float* __restrict__ A1 = g_agg;
    float* __restrict__ out = pick_out(osel, nullptr);

    __shared__ uint32_t As[128][20];
    __shared__ uint32_t Bs[16][136];

    const int tid  = threadIdx.x;
    const int lane = tid & 31;
    const int wid  = tid >> 5;
    const int row0 = blockIdx.x * 128;

    float c[16][4];
    #pragma unroll
    for (int t = 0; t < 16; t++)
        #pragma unroll
        for (int j = 0; j < 4; j++) c[t][j] = 0.f;

    const int ar = tid >> 1;            // A stage row 0..127
    const int ak = (tid & 1) * 8;       // A stage k-offset 0/8
    const int bk = tid >> 4;            // B stage k-row 0..15
    const int bn = (tid & 15) * 8;      // B stage col 0..120

    #pragma unroll 1
    for (int kb = 0; kb < 16; ++kb) {
        const float* __restrict__ A = (kb >= 8) ? A1 : A0;
        const float* __restrict__ B = (kb >= 8) ? B1 : B0;
        const int kBase = (kb * 16) & 127;

        float a[8];
        const int grow = row0 + ar;
        if (grow < NN) {
            const float* p = A + (size_t)grow * 128 + kBase + ak;
            *(float4*)&a[0] = *(const float4*)(p);
            *(float4*)&a[4] = *(const float4*)(p + 4);
        } else {
            #pragma unroll
            for (int j = 0; j < 8; j++) a[j] = 0.f;
        }
        float b[8];
        {
            const float* p = B + (size_t)(kBase + bk) * 128 + bn;
            *(float4*)&b[0] = *(const float4*)(p);
            *(float4*)&b[4] = *(const float4*)(p + 4);
        }

        __syncthreads();
        {
            uint4 u0, u1;
            u0.x = f2tf(a[0]); u0.y = f2tf(a[1]); u0.z = f2tf(a[2]); u0.w = f2tf(a[3]);
            u1.x = f2tf(a[4]); u1.y = f2tf(a[5]); u1.z = f2tf(a[6]); u1.w = f2tf(a[7]);
            *(uint4*)&As[ar][ak]     = u0;
            *(uint4*)&As[ar][ak + 4] = u1;
            u0.x = f2tf(b[0]); u0.y = f2tf(b[1]); u0.z = f2tf(b[2]); u0.w = f2tf(b[3]);
            u1.x = f2tf(b[4]); u1.y = f2tf(b[5]); u1.z = f2tf(b[6]); u1.w = f2tf(b[7]);
            *(uint4*)&Bs[bk][bn]     = u0;
            *(uint4*)&Bs[bk][bn + 4] = u1;
        }
        __syncthreads();

        const int fr = wid * 16 + (lane >> 2);   // fragment row (block-local)
        const int fc = lane & 3;                 // fragment k within k8
        #pragma unroll
        for (int ks = 0; ks < 2; ks++) {
            const int k0 = ks * 8;
            uint32_t a0 = As[fr][k0 + fc];
            uint32_t a1 = As[fr + 8][k0 + fc];
            uint32_t a2 = As[fr][k0 + fc + 4];
            uint32_t a3 = As[fr + 8][k0 + fc + 4];
            #pragma unroll
            for (int t = 0; t < 16; t++) {
                uint32_t b0 = Bs[k0 + fc][t * 8 + (lane >> 2)];
                uint32_t b1 = Bs[k0 + fc + 4][t * 8 + (lane >> 2)];
                mma_tf32(c[t], a0, a1, a2, a3, b0, b1);
            }
        }
    }

    // ---- epilogue: bias + mask/gh + relu, rows r0 and r0+8 -----------------
    const int m4 = g_mask4;
    #pragma unroll
    for (int half = 0; half < 2; half++) {
        const int r = row0 + wid * 16 + (lane >> 2) + half * 8;
        if (r >= NN) continue;
        bool mb = m4 ? (((const unsigned int*)maskp)[r] != 0u)
                     : (((const unsigned char*)maskp)[r] != 0);
        const float* gr = mb ? nullptr : (gh + (size_t)g2[r] * 128);
        #pragma unroll
        for (int t = 0; t < 16; t++) {
            const int cc = t * 8 + 2 * (lane & 3);
            float v0 = c[t][half * 2 + 0];
            float v1 = c[t][half * 2 + 1];
            float2 bv = *(const float2*)&bias[cc];
            v0 += bv.x; v1 += bv.y;
            if (!mb) {
                float2 gv = *(const float2*)&gr[cc];
                v0 = gv.x; v1 = gv.y;
            }
            v0 = fmaxf(v0, 0.f);
            v1 = fmaxf(v1, 0.f);
            float2 o; o.x = v0; o.y = v1;
            *(float2*)&out[(size_t)r * 128 + cc] = o;
        }
    }
}

// ---------------- FFMA2 GEMM (layer 3, exact fp32) --------------------------
// BM=128, BK=16, TM=8, K=128 (KT=8). BN=64, TN=4.
// ADDM=1: v += g_t40[r].  ZBIAS=1: bias = 0.
template<int BN, int TN, int KT, int ADDM, int ZBIAS>
__global__ void __launch_bounds__(256)
k_gemm(int a0sel, const float* __restrict__ A0p,
       const float* __restrict__ B0,
       const float* __restrict__ bias,
       int osel, float* __restrict__ outp, int Nout)
{
    constexpr int BM = 128, BK = 16, TM = 8;
    constexpr int TX = BN / TN;
    constexpr int BLD = BK * BN / 256;
    constexpr int TN2 = TN / 2;

    const float* __restrict__ A0 = pick_in(a0sel, A0p);
    float* __restrict__ out = pick_out(osel, outp);

    __shared__ float As[BK][BM];
    __shared__ float Bs[BK][BN];

    const int tid = threadIdx.x;
    const int tx  = tid % TX;
    const int ty  = tid / TX;
    const int row0 = blockIdx.x * BM;

    unsigned long long acc2[TM][TN2];
    #pragma unroll
    for (int i = 0; i < TM; i++)
        #pragma unroll
        for (int j = 0; j < TN2; j++) acc2[i][j] = 0ull;

    const int ar = tid >> 1;
    const int ak = (tid & 1) * 8;
    const int bk = (tid * BLD) / BN;
    const int bn = (tid * BLD) % BN;

    #pragma unroll 1
    for (int kb = 0; kb < KT; ++kb) {
        const float* __restrict__ A = A0;
        const float* __restrict__ B = B0;
        const int kBase = (kb * BK) & 127;

        float4 a0, a1;
        const int grow = row0 + ar;
        if (grow < NN) {
            const float* p = A + (size_t)grow * 128 + kBase + ak;
            a0 = *(const float4*)(p);
            a1 = *(const float4*)(p + 4);
        } else {
            a0 = make_float4(0.f, 0.f, 0.f, 0.f);
            a1 = a0;
        }
        float4 bv[BLD / 4];
        #pragma unroll
        for (int q = 0; q < BLD / 4; q++) {
            const int nn = bn + q * 4;
            if (nn < Nout)
                bv[q] = *(const float4*)(B + (size_t)(kBase + bk) * Nout + nn);
            else
                bv[q] = make_float4(0.f, 0.f, 0.f, 0.f);
        }

        __syncthreads();
        As[ak + 0][ar] = a0.x; As[ak + 1][ar] = a0.y;
        As[ak + 2][ar] = a0.z; As[ak + 3][ar] = a0.w;
        As[ak + 4][ar] = a1.x; As[ak + 5][ar] = a1.y;
        As[ak + 6][ar] = a1.z; As[ak + 7][ar] = a1.w;
        #pragma unroll
        for (int q = 0; q < BLD / 4; q++)
            *(float4*)&Bs[bk][bn + q * 4] = bv[q];
        __syncthreads();

        #pragma unroll
        for (int kk = 0; kk < BK; kk++) {
            float af[TM];
            *(float4*)&af[0] = *(const float4*)&As[kk][ty * TM];
            *(float4*)&af[4] = *(const float4*)&As[kk][ty * TM + 4];
            unsigned long long bp[TN2];
            #pragma unroll
            for (int q = 0; q < TN2; q++)
                bp[q] = *(const unsigned long long*)&Bs[kk][tx * TN + 2 * q];
            #pragma unroll
            for (int i = 0; i < TM; i++) {
                unsigned long long ap = pack_dup(af[i]);
                #pragma unroll
                for (int j = 0; j < TN2; j++)
                    ffma2(acc2[i][j], ap, bp[j]);
            }
        }
    }

    const int c0 = tx * TN;
    float bfr[TN];
    #pragma unroll
    for (int j = 0; j < TN; j++)
        bfr[j] = (!ZBIAS && c0 + j < Nout) ? bias[c0 + j] : 0.f;

    #pragma unroll
    for (int i = 0; i < TM; i++) {
        const int r = row0 + ty * TM + i;
        if (r >= NN) continue;
        float vals[TN];
        #pragma unroll
        for (int j = 0; j < TN2; j++) {
            float2 v = unpack2(acc2[i][j]);
            vals[2 * j + 0] = v.x + bfr[2 * j + 0];
            vals[2 * j + 1] = v.y + bfr[2 * j + 1];
        }
        if (ADDM && c0 < Nout) {
            const float* am = g_t40 + (size_t)r * NC + c0;
            #pragma unroll
            for (int q = 0; q < TN / 4; q++) {
                if (c0 + q * 4 < Nout) {
                    float4 av = *(const float4*)(am + q * 4);
                    vals[q * 4 + 0] += av.x; vals[q * 4 + 1] += av.y;
                    vals[q * 4 + 2] += av.z; vals[q * 4 + 3] += av.w;
                }
            }
        }
        float* orow = out + (size_t)r * Nout + c0;
        if (c0 + TN <= Nout) {
            #pragma unroll
            for (int q = 0; q < TN / 4; q++)
                *(float4*)(orow + q * 4) = *(const float4*)&vals[q * 4];
        } else if (c0 < Nout) {
            for (int j = 0; j < TN && c0 + j < Nout; j++) orow[j] = vals[j];
        }
    }
}

// ---------------- launch ----------------------------------------------------
extern "C" void kernel_launch(void* const* d_in, const int* in_sizes, int n_in,
                              void* d_out, int out_size)
{
    const float* feat = (const float*)d_in[0];
    const float* gh   = (const float*)d_in[1];
    const float* gh2  = (const float*)d_in[2];
    const float* W1s  = (const float*)d_in[3];
    const float* W1n  = (const float*)d_in[4];
    const float* b1   = (const float*)d_in[5];
    const float* W2s  = (const float*)d_in[6];
    const float* W2n  = (const float*)d_in[7];
    const float* b2   = (const float*)d_in[8];
    const float* W3s  = (const float*)d_in[9];
    const float* W3n  = (const float*)d_in[10];
    const float* b3   = (const float*)d_in[11];
    const int*   esrc = (const int*)d_in[12];
    const int*   edst = (const int*)d_in[13];
    const int*   g2   = (const int*)d_in[14];
    const void*  mask = (const void*)d_in[15];
    float* out = (float*)d_out;

    const int TB = 256;
    const int scanBlocks = (NN + 1023) / 1024;

    k_setup<<<(NN + TB - 1) / TB, TB>>>((const unsigned int*)mask);
    k_hist<<<(NE + TB - 1) / TB, TB>>>(edst);
    k_scanA<<<scanBlocks, 1024>>>();
    k_scanC<<<(NN + TB - 1) / TB, TB>>>(scanBlocks);
    k_scatter<<<(NE + TB - 1) / TB, TB>>>(esrc, edst);

    const int aggBlocks  = (NN * 32 + TB - 1) / TB;
    const int gemmBlocks = (NN + 127) / 128;

    // Layer 1 (TF32 tensor cores)
    k_agg<<<aggBlocks, TB>>>(0, feat);
    k_gemm_tc<<<gemmBlocks, TB>>>(0, feat, W1s, W1n, b1, 1, mask, gh, g2);
    // Layer 2 (TF32 tensor cores)
    k_agg<<<aggBlocks, TB>>>(1, nullptr);
    k_gemm_tc<<<gemmBlocks, TB>>>(1, nullptr, W2s, W2n, b2, 2, mask, gh2, g2);
    // Layer 3 transform-first (exact fp32): t = hB @ W3n -> g_tA; agg40;
    // out = hB @ W3s + g_t40 + b3
    k_gemm<64, 4, 8, 0, 1><<<gemmBlocks, TB>>>(2, nullptr, W3n, nullptr,
            3, nullptr, NC);
    k_agg40<<<aggBlocks, TB>>>();
    k_gemm<64, 4, 8, 1, 0><<<gemmBlocks, TB>>>(2, nullptr, W3s, b3,
            0, out, NC);
}

// round 14
// speedup vs baseline: 1.4924x; 1.0167x over previous
#include <cuda_runtime.h>
#include <cuda_bf16.h>
#include <cuda_fp16.h>
#include <stdint.h>

#define NN 100000
#define NE 1600000
#define FD 128
#define NC 40

__device__ int    g_deg[NN];
__device__ int    g_start[NN];
__device__ int    g_cursor[NN];
__device__ float  g_invdeg[NN];
__device__ int    g_csr[NE];
__device__ float  g_hA[(size_t)NN * FD];
__device__ float  g_hB[(size_t)NN * FD];
__device__ float  g_agg[(size_t)NN * FD];
__device__ __half g_h16[(size_t)NN * FD];   // fp16 gather copy (feat, then hA)
__device__ float  g_tA[(size_t)NN * NC];
__device__ float  g_t40[(size_t)NN * NC];
__device__ int    g_mask4;
__device__ int    g_blockSums[128];

__device__ __forceinline__ const float* pick_in(int sel, const float* p) {
    if (sel == 1) return g_hA;
    if (sel == 2) return g_hB;
    return p;
}
__device__ __forceinline__ float* pick_out(int sel, float* p) {
    if (sel == 1) return g_hA;
    if (sel == 2) return g_hB;
    if (sel == 3) return g_tA;
    return p;
}

__device__ __forceinline__ unsigned long long pack_dup(float a) {
    unsigned long long r;
    asm("mov.b64 %0, {%1, %1};" : "=l"(r) : "f"(a));
    return r;
}
__device__ __forceinline__ void ffma2(unsigned long long& d,
                                      unsigned long long a,
                                      unsigned long long b) {
    asm("fma.rn.f32x2 %0, %1, %2, %0;" : "+l"(d) : "l"(a), "l"(b));
}
__device__ __forceinline__ float2 unpack2(unsigned long long v) {
    float2 r;
    asm("mov.b64 {%0, %1}, %2;" : "=f"(r.x), "=f"(r.y) : "l"(v));
    return r;
}
__device__ __forceinline__ uint32_t f2tf(float f) {
    uint32_t r;
    asm("cvt.rna.tf32.f32 %0, %1;" : "=r"(r) : "f"(f));
    return r;
}
__device__ __forceinline__ void mma_tf32(float* c,
                                         uint32_t a0, uint32_t a1,
                                         uint32_t a2, uint32_t a3,
                                         uint32_t b0, uint32_t b1) {
    asm("mma.sync.aligned.m16n8k8.row.col.f32.tf32.tf32.f32 "
        "{%0,%1,%2,%3}, {%4,%5,%6,%7}, {%8,%9}, {%0,%1,%2,%3};"
        : "+f"(c[0]), "+f"(c[1]), "+f"(c[2]), "+f"(c[3])
        : "r"(a0), "r"(a1), "r"(a2), "r"(a3), "r"(b0), "r"(b1));
}

// ---------------- setup: zero deg + mask dtype probe ------------------------
__global__ void k_setup(const unsigned int* __restrict__ m) {
    int i = blockIdx.x * blockDim.x + threadIdx.x;
    if (i < NN) g_deg[i] = 0;
    if (blockIdx.x == 0 && threadIdx.x < 32) {
        int lane = threadIdx.x;
        unsigned bad = 0;
        for (int j = lane; j < 64; j += 32) {
            unsigned v = m[j];
            if (!(v == 0u || v == 1u || v == 0x3F800000u)) bad = 1;
        }
        unsigned any = __ballot_sync(0xFFFFFFFFu, bad);
        if (lane == 0) g_mask4 = (any == 0u) ? 1 : 0;
    }
}

__global__ void k_hist(const int* __restrict__ dst) {
    int i = blockIdx.x * blockDim.x + threadIdx.x;
    if (i < NE) atomicAdd(&g_deg[dst[i]], 1);
}

// ---------------- fp32 -> fp16 row copy (feat) ------------------------------
__global__ void k_cvt(const float* __restrict__ src) {
    int i = blockIdx.x * blockDim.x + threadIdx.x;   // 8 elems per thread
    if (i >= NN * FD / 8) return;
    const float4* p = (const float4*)(src) + 2 * i;
    float4 a = p[0], b = p[1];
    __half2 h0 = __floats2half2_rn(a.x, a.y);
    __half2 h1 = __floats2half2_rn(a.z, a.w);
    __half2 h2 = __floats2half2_rn(b.x, b.y);
    __half2 h3 = __floats2half2_rn(b.z, b.w);
    uint4 o;
    o.x = *(uint32_t*)&h0; o.y = *(uint32_t*)&h1;
    o.z = *(uint32_t*)&h2; o.w = *(uint32_t*)&h3;
    ((uint4*)g_h16)[i] = o;
}

// ---------------- hierarchical exclusive scan -------------------------------
__global__ void __launch_bounds__(1024) k_scanA() {
    const int tid  = threadIdx.x;
    const int lane = tid & 31;
    const int wid  = tid >> 5;
    const int i    = blockIdx.x * 1024 + tid;

    int v = (i < NN) ? g_deg[i] : 0;
    int x = v;
    #pragma unroll
    for (int off = 1; off < 32; off <<= 1) {
        int y = __shfl_up_sync(0xFFFFFFFFu, x, off);
        if (lane >= off) x += y;
    }
    __shared__ int wsum[32];
    if (lane == 31) wsum[wid] = x;
    __syncthreads();
    if (wid == 0) {
        int w = wsum[lane];
        #pragma unroll
        for (int off = 1; off < 32; off <<= 1) {
            int y = __shfl_up_sync(0xFFFFFFFFu, w, off);
            if (lane >= off) w += y;
        }
        wsum[lane] = w;
    }
    __syncthreads();
    int base = (wid > 0) ? wsum[wid - 1] : 0;
    int incl = x + base;
    if (i < NN) g_start[i] = incl - v;
    if (tid == 1023) g_blockSums[blockIdx.x] = incl;
}

__global__ void k_scanC(int nblk) {
    const int t = threadIdx.x;
    const int B = (blockIdx.x * 256) >> 10;
    __shared__ int wsum[8];
    __shared__ int s_off;
    int v = (t < B) ? g_blockSums[t] : 0;
    #pragma unroll
    for (int off = 16; off > 0; off >>= 1)
        v += __shfl_down_sync(0xFFFFFFFFu, v, off);
    if ((t & 31) == 0) wsum[t >> 5] = v;
    __syncthreads();
    if (t == 0) {
        int s = 0;
        #pragma unroll
        for (int w = 0; w < 8; w++) s += wsum[w];
        s_off = s;
    }
    __syncthreads();
    int i = blockIdx.x * 256 + t;
    if (i < NN) {
        int st = g_start[i] + s_off;
        g_start[i]  = st;
        g_cursor[i] = st;
        int d = g_deg[i];
        g_invdeg[i] = 1.0f / (float)(d > 0 ? d : 1);
    }
}

__global__ void k_scatter(const int* __restrict__ src, const int* __restrict__ dst) {
    int i = blockIdx.x * blockDim.x + threadIdx.x;
    if (i < NE) {
        int d = dst[i];
        int p = atomicAdd(&g_cursor[d], 1);
        g_csr[p] = src[i];
    }
}

// ---------------- mean aggregation from fp16 rows (warp per node) -----------
// Row = 128 halves = 256B. Lane owns 4 cols: uint2 load, fp32 accumulate.
__global__ void k_agg16() {
    const __half* __restrict__ h = g_h16;
    int gw   = (blockIdx.x * blockDim.x + threadIdx.x) >> 5;
    int lane = threadIdx.x & 31;
    if (gw >= NN) return;
    int s = g_start[gw];
    int d = g_deg[gw];
    float4 acc0 = make_float4(0.f, 0.f, 0.f, 0.f);
    float4 acc1 = make_float4(0.f, 0.f, 0.f, 0.f);
    int e = 0;
    for (; e + 1 < d; e += 2) {
        int s0 = g_csr[s + e];
        int s1 = g_csr[s + e + 1];
        uint2 u0 = *(const uint2*)(h + (size_t)s0 * FD + lane * 4);
        uint2 u1 = *(const uint2*)(h + (size_t)s1 * FD + lane * 4);
        float2 a0 = __half22float2(*(__half2*)&u0.x);
        float2 a1 = __half22float2(*(__half2*)&u0.y);
        float2 b0 = __half22float2(*(__half2*)&u1.x);
        float2 b1 = __half22float2(*(__half2*)&u1.y);
        acc0.x += a0.x; acc0.y += a0.y; acc0.z += a1.x; acc0.w += a1.y;
        acc1.x += b0.x; acc1.y += b0.y; acc1.z += b1.x; acc1.w += b1.y;
    }
    if (e < d) {
        int s0 = g_csr[s + e];
        uint2 u0 = *(const uint2*)(h + (size_t)s0 * FD + lane * 4);
        float2 a0 = __half22float2(*(__half2*)&u0.x);
        float2 a1 = __half22float2(*(__half2*)&u0.y);
        acc0.x += a0.x; acc0.y += a0.y; acc0.z += a1.x; acc0.w += a1.y;
    }
    float iv = g_invdeg[gw];
    float4 r;
    r.x = (acc0.x + acc1.x) * iv;
    r.y = (acc0.y + acc1.y) * iv;
    r.z = (acc0.z + acc1.z) * iv;
    r.w = (acc0.w + acc1.w) * iv;
    *(float4*)(g_agg + (size_t)gw * FD + lane * 4) = r;
}

// ---------------- mean aggregation, 40-wide (lanes 0-9 of each warp) --------
__global__ void k_agg40() {
    const float* __restrict__ t = g_tA;
    int gw   = (blockIdx.x * blockDim.x + threadIdx.x) >> 5;
    int lane = threadIdx.x & 31;
    if (gw >= NN) return;
    int s = g_start[gw];
    int d = g_deg[gw];
    float4 acc0 = make_float4(0.f, 0.f, 0.f, 0.f);
    float4 acc1 = make_float4(0.f, 0.f, 0.f, 0.f);
    const bool act = (lane < 10);
    int e = 0;
    for (; e + 1 < d; e += 2) {
        int s0 = g_csr[s + e];
        int s1 = g_csr[s + e + 1];
        if (act) {
            float4 v0 = *(const float4*)(t + (size_t)s0 * NC + lane * 4);
            float4 v1 = *(const float4*)(t + (size_t)s1 * NC + lane * 4);
            acc0.x += v0.x; acc0.y += v0.y; acc0.z += v0.z; acc0.w += v0.w;
            acc1.x += v1.x; acc1.y += v1.y; acc1.z += v1.z; acc1.w += v1.w;
        }
    }
    if (e < d && act) {
        int s0 = g_csr[s + e];
        float4 v0 = *(const float4*)(t + (size_t)s0 * NC + lane * 4);
        acc0.x += v0.x; acc0.y += v0.y; acc0.z += v0.z; acc0.w += v0.w;
    }
    if (act) {
        float iv = g_invdeg[gw];
        float4 r;
        r.x = (acc0.x + acc1.x) * iv;
        r.y = (acc0.y + acc1.y) * iv;
        r.z = (acc0.z + acc1.z) * iv;
        r.w = (acc0.w + acc1.w) * iv;
        *(float4*)(g_t40 + (size_t)gw * NC + lane * 4) = r;
    }
}

// ---------------- TF32 tensor-core GEMM (layers 1 & 2) ----------------------
// out = relu( mask ? ([h|agg] @ [Bself;Bneigh] + bias) : gh[g2] )
// WR16=1: also store fp16 copy of the output row into g_h16.
template<int WR16>
__global__ void __launch_bounds__(256)
k_gemm_tc(int a0sel, const float* __restrict__ A0p,
          const float* __restrict__ B0, const float* __restrict__ B1,
          const float* __restrict__ bias,
          int osel,
          const void* __restrict__ maskp,
          const float* __restrict__ gh, const int* __restrict__ g2)
{
    const float* __restrict__ A0 = pick_in(a0sel, A0p);
    const float* __restrict__ A1 = g_agg;
    float* __restrict__ out = pick_out(osel, nullptr);

    __shared__ uint32_t As[128][20];
    __shared__ uint32_t Bs[16][136];

    const int tid  = threadIdx.x;
    const int lane = tid & 31;
    const int wid  = tid >> 5;
    const int row0 = blockIdx.x * 128;

    float c[16][4];
    #pragma unroll
    for (int t = 0; t < 16; t++)
        #pragma unroll
        for (int j = 0; j < 4; j++) c[t][j] = 0.f;

    const int ar = tid >> 1;
    const int ak = (tid & 1) * 8;
    const int bk = tid >> 4;
    const int bn = (tid & 15) * 8;

    #pragma unroll 1
    for (int kb = 0; kb < 16; ++kb) {
        const float* __restrict__ A = (kb >= 8) ? A1 : A0;
        const float* __restrict__ B = (kb >= 8) ? B1 : B0;
        const int kBase = (kb * 16) & 127;

        float a[8];
        const int grow = row0 + ar;
        if (grow < NN) {
            const float* p = A + (size_t)grow * 128 + kBase + ak;
            *(float4*)&a[0] = *(const float4*)(p);
            *(float4*)&a[4] = *(const float4*)(p + 4);
        } else {
            #pragma unroll
            for (int j = 0; j < 8; j++) a[j] = 0.f;
        }
        float b[8];
        {
            const float* p = B + (size_t)(kBase + bk) * 128 + bn;
            *(float4*)&b[0] = *(const float4*)(p);
            *(float4*)&b[4] = *(const float4*)(p + 4);
        }

        __syncthreads();
        {
            uint4 u0, u1;
            u0.x = f2tf(a[0]); u0.y = f2tf(a[1]); u0.z = f2tf(a[2]); u0.w = f2tf(a[3]);
            u1.x = f2tf(a[4]); u1.y = f2tf(a[5]); u1.z = f2tf(a[6]); u1.w = f2tf(a[7]);
            *(uint4*)&As[ar][ak]     = u0;
            *(uint4*)&As[ar][ak + 4] = u1;
            u0.x = f2tf(b[0]); u0.y = f2tf(b[1]); u0.z = f2tf(b[2]); u0.w = f2tf(b[3]);
            u1.x = f2tf(b[4]); u1.y = f2tf(b[5]); u1.z = f2tf(b[6]); u1.w = f2tf(b[7]);
            *(uint4*)&Bs[bk][bn]     = u0;
            *(uint4*)&Bs[bk][bn + 4] = u1;
        }
        __syncthreads();

        const int fr = wid * 16 + (lane >> 2);
        const int fc = lane & 3;
        #pragma unroll
        for (int ks = 0; ks < 2; ks++) {
            const int k0 = ks * 8;
            uint32_t a0 = As[fr][k0 + fc];
            uint32_t a1 = As[fr + 8][k0 + fc];
            uint32_t a2 = As[fr][k0 + fc + 4];
            uint32_t a3 = As[fr + 8][k0 + fc + 4];
            #pragma unroll
            for (int t = 0; t < 16; t++) {
                uint32_t b0 = Bs[k0 + fc][t * 8 + (lane >> 2)];
                uint32_t b1 = Bs[k0 + fc + 4][t * 8 + (lane >> 2)];
                mma_tf32(c[t], a0, a1, a2, a3, b0, b1);
            }
        }
    }

    // ---- epilogue ----
    const int m4 = g_mask4;
    #pragma unroll
    for (int half = 0; half < 2; half++) {
        const int r = row0 + wid * 16 + (lane >> 2) + half * 8;
        if (r >= NN) continue;
        bool mb = m4 ? (((const unsigned int*)maskp)[r] != 0u)
                     : (((const unsigned char*)maskp)[r] != 0);
        const float* gr = mb ? nullptr : (gh + (size_t)g2[r] * 128);
        #pragma unroll
        for (int t = 0; t < 16; t++) {
            const int cc = t * 8 + 2 * (lane & 3);
            float v0 = c[t][half * 2 + 0];
            float v1 = c[t][half * 2 + 1];
            float2 bv = *(const float2*)&bias[cc];
            v0 += bv.x; v1 += bv.y;
            if (!mb) {
                float2 gv = *(const float2*)&gr[cc];
                v0 = gv.x; v1 = gv.y;
            }
            v0 = fmaxf(v0, 0.f);
            v1 = fmaxf(v1, 0.f);
            float2 o; o.x = v0; o.y = v1;
            *(float2*)&out[(size_t)r * 128 + cc] = o;
            if (WR16) {
                __half2 h2 = __floats2half2_rn(v0, v1);
                *(uint32_t*)(g_h16 + (size_t)r * 128 + cc) = *(uint32_t*)&h2;
            }
        }
    }
}

// ---------------- FFMA2 GEMM (layer 3, exact fp32) --------------------------
template<int BN, int TN, int KT, int ADDM, int ZBIAS>
__global__ void __launch_bounds__(256)
k_gemm(int a0sel, const float* __restrict__ A0p,
       const float* __restrict__ B0,
       const float* __restrict__ bias,
       int osel, float* __restrict__ outp, int Nout)
{
    constexpr int BM = 128, BK = 16, TM = 8;
    constexpr int TX = BN / TN;
    constexpr int BLD = BK * BN / 256;
    constexpr int TN2 = TN / 2;

    const float* __restrict__ A0 = pick_in(a0sel, A0p);
    float* __restrict__ out = pick_out(osel, outp);

    __shared__ float As[BK][BM];
    __shared__ float Bs[BK][BN];

    const int tid = threadIdx.x;
    const int tx  = tid % TX;
    const int ty  = tid / TX;
    const int row0 = blockIdx.x * BM;

    unsigned long long acc2[TM][TN2];
    #pragma unroll
    for (int i = 0; i < TM; i++)
        #pragma unroll
        for (int j = 0; j < TN2; j++) acc2[i][j] = 0ull;

    const int ar = tid >> 1;
    const int ak = (tid & 1) * 8;
    const int bk = (tid * BLD) / BN;
    const int bn = (tid * BLD) % BN;

    #pragma unroll 1
    for (int kb = 0; kb < KT; ++kb) {
        const float* __restrict__ A = A0;
        const float* __restrict__ B = B0;
        const int kBase = (kb * BK) & 127;

        float4 a0, a1;
        const int grow = row0 + ar;
        if (grow < NN) {
            const float* p = A + (size_t)grow * 128 + kBase + ak;
            a0 = *(const float4*)(p);
            a1 = *(const float4*)(p + 4);
        } else {
            a0 = make_float4(0.f, 0.f, 0.f, 0.f);
            a1 = a0;
        }
        float4 bv[BLD / 4];
        #pragma unroll
        for (int q = 0; q < BLD / 4; q++) {
            const int nn = bn + q * 4;
            if (nn < Nout)
                bv[q] = *(const float4*)(B + (size_t)(kBase + bk) * Nout + nn);
            else
                bv[q] = make_float4(0.f, 0.f, 0.f, 0.f);
        }

        __syncthreads();
        As[ak + 0][ar] = a0.x; As[ak + 1][ar] = a0.y;
        As[ak + 2][ar] = a0.z; As[ak + 3][ar] = a0.w;
        As[ak + 4][ar] = a1.x; As[ak + 5][ar] = a1.y;
        As[ak + 6][ar] = a1.z; As[ak + 7][ar] = a1.w;
        #pragma unroll
        for (int q = 0; q < BLD / 4; q++)
            *(float4*)&Bs[bk][bn + q * 4] = bv[q];
        __syncthreads();

        #pragma unroll
        for (int kk = 0; kk < BK; kk++) {
            float af[TM];
            *(float4*)&af[0] = *(const float4*)&As[kk][ty * TM];
            *(float4*)&af[4] = *(const float4*)&As[kk][ty * TM + 4];
            unsigned long long bp[TN2];
            #pragma unroll
            for (int q = 0; q < TN2; q++)
                bp[q] = *(const unsigned long long*)&Bs[kk][tx * TN + 2 * q];
            #pragma unroll
            for (int i = 0; i < TM; i++) {
                unsigned long long ap = pack_dup(af[i]);
                #pragma unroll
                for (int j = 0; j < TN2; j++)
                    ffma2(acc2[i][j], ap, bp[j]);
            }
        }
    }

    const int c0 = tx * TN;
    float bfr[TN];
    #pragma unroll
    for (int j = 0; j < TN; j++)
        bfr[j] = (!ZBIAS && c0 + j < Nout) ? bias[c0 + j] : 0.f;

    #pragma unroll
    for (int i = 0; i < TM; i++) {
        const int r = row0 + ty * TM + i;
        if (r >= NN) continue;
        float vals[TN];
        #pragma unroll
        for (int j = 0; j < TN2; j++) {
            float2 v = unpack2(acc2[i][j]);
            vals[2 * j + 0] = v.x + bfr[2 * j + 0];
            vals[2 * j + 1] = v.y + bfr[2 * j + 1];
        }
        if (ADDM && c0 < Nout) {
            const float* am = g_t40 + (size_t)r * NC + c0;
            #pragma unroll
            for (int q = 0; q < TN / 4; q++) {
                if (c0 + q * 4 < Nout) {
                    float4 av = *(const float4*)(am + q * 4);
                    vals[q * 4 + 0] += av.x; vals[q * 4 + 1] += av.y;
                    vals[q * 4 + 2] += av.z; vals[q * 4 + 3] += av.w;
                }
            }
        }
        float* orow = out + (size_t)r * Nout + c0;
        if (c0 + TN <= Nout) {
            #pragma unroll
            for (int q = 0; q < TN / 4; q++)
                *(float4*)(orow + q * 4) = *(const float4*)&vals[q * 4];
        } else if (c0 < Nout) {
            for (int j = 0; j < TN && c0 + j < Nout; j++) orow[j] = vals[j];
        }
    }
}

// ---------------- launch ----------------------------------------------------
extern "C" void kernel_launch(void* const* d_in, const int* in_sizes, int n_in,
                              void* d_out, int out_size)
{
    const float* feat = (const float*)d_in[0];
    const float* gh   = (const float*)d_in[1];
    const float* gh2  = (const float*)d_in[2];
    const float* W1s  = (const float*)d_in[3];
    const float* W1n  = (const float*)d_in[4];
    const float* b1   = (const float*)d_in[5];
    const float* W2s  = (const float*)d_in[6];
    const float* W2n  = (const float*)d_in[7];
    const float* b2   = (const float*)d_in[8];
    const float* W3s  = (const float*)d_in[9];
    const float* W3n  = (const float*)d_in[10];
    const float* b3   = (const float*)d_in[11];
    const int*   esrc = (const int*)d_in[12];
    const int*   edst = (const int*)d_in[13];
    const int*   g2   = (const int*)d_in[14];
    const void*  mask = (const void*)d_in[15];
    float* out = (float*)d_out;

    const int TB = 256;
    const int scanBlocks = (NN + 1023) / 1024;

    k_setup<<<(NN + TB - 1) / TB, TB>>>((const unsigned int*)mask);
    k_hist<<<(NE + TB - 1) / TB, TB>>>(edst);
    k_cvt<<<(NN * FD / 8 + TB - 1) / TB, TB>>>(feat);     // feat -> fp16
    k_scanA<<<scanBlocks, 1024>>>();
    k_scanC<<<(NN + TB - 1) / TB, TB>>>(scanBlocks);
    k_scatter<<<(NE + TB - 1) / TB, TB>>>(esrc, edst);

    const int aggBlocks  = (NN * 32 + TB - 1) / TB;
    const int gemmBlocks = (NN + 127) / 128;

    // Layer 1: agg16(fp16 feat) -> g_agg; GEMM writes hA + fp16 copy
    k_agg16<<<aggBlocks, TB>>>();
    k_gemm_tc<1><<<gemmBlocks, TB>>>(0, feat, W1s, W1n, b1, 1, mask, gh, g2);
    // Layer 2: agg16(fp16 hA) -> g_agg; GEMM writes hB
    k_agg16<<<aggBlocks, TB>>>();
    k_gemm_tc<0><<<gemmBlocks, TB>>>(1, nullptr, W2s, W2n, b2, 2, mask, gh2, g2);
    // Layer 3 transform-first (exact fp32): t = hB @ W3n -> g_tA; agg40;
    // out = hB @ W3s + g_t40 + b3
    k_gemm<64, 4, 8, 0, 1><<<gemmBlocks, TB>>>(2, nullptr, W3n, nullptr,
            3, nullptr, NC);
    k_agg40<<<aggBlocks, TB>>>();
    k_gemm<64, 4, 8, 1, 0><<<gemmBlocks, TB>>>(2, nullptr, W3s, b3,
            0, out, NC);
}

// round 15
// speedup vs baseline: 1.7296x; 1.1590x over previous
#include <cuda_runtime.h>
#include <cuda_bf16.h>
#include <cuda_fp16.h>
#include <stdint.h>

#define NN 100000
#define NE 1600000
#define FD 128
#define NC 40

__device__ int    g_deg[NN];
__device__ int    g_start[NN];
__device__ int    g_cursor[NN];
__device__ float  g_invdeg[NN];
__device__ int    g_csr[NE];
__device__ float  g_hA[(size_t)NN * FD];
__device__ float  g_hB[(size_t)NN * FD];
__device__ float  g_agg[(size_t)NN * FD];
__device__ __half g_h16[(size_t)NN * FD];   // fp16 gather copy (feat, then hA)
__device__ float  g_tA[(size_t)NN * NC];    // hB @ W3n
__device__ float  g_tS[(size_t)NN * NC];    // hB @ W3s + b3
__device__ float  g_t40[(size_t)NN * NC];   // agg40(tA)
__device__ int    g_mask4;
__device__ int    g_blockSums[128];

__device__ __forceinline__ const float* pick_in(int sel, const float* p) {
    if (sel == 1) return g_hA;
    if (sel == 2) return g_hB;
    return p;
}
__device__ __forceinline__ float* pick_out(int sel, float* p) {
    if (sel == 1) return g_hA;
    if (sel == 2) return g_hB;
    return p;
}

__device__ __forceinline__ uint32_t f2tf(float f) {
    uint32_t r;
    asm("cvt.rna.tf32.f32 %0, %1;" : "=r"(r) : "f"(f));
    return r;
}
__device__ __forceinline__ void mma_tf32(float* c,
                                         uint32_t a0, uint32_t a1,
                                         uint32_t a2, uint32_t a3,
                                         uint32_t b0, uint32_t b1) {
    asm("mma.sync.aligned.m16n8k8.row.col.f32.tf32.tf32.f32 "
        "{%0,%1,%2,%3}, {%4,%5,%6,%7}, {%8,%9}, {%0,%1,%2,%3};"
        : "+f"(c[0]), "+f"(c[1]), "+f"(c[2]), "+f"(c[3])
        : "r"(a0), "r"(a1), "r"(a2), "r"(a3), "r"(b0), "r"(b1));
}

// ---------------- setup: zero deg + mask dtype probe ------------------------
__global__ void k_setup(const unsigned int* __restrict__ m) {
    int i = blockIdx.x * blockDim.x + threadIdx.x;
    if (i < NN) g_deg[i] = 0;
    if (blockIdx.x == 0 && threadIdx.x < 32) {
        int lane = threadIdx.x;
        unsigned bad = 0;
        for (int j = lane; j < 64; j += 32) {
            unsigned v = m[j];
            if (!(v == 0u || v == 1u || v == 0x3F800000u)) bad = 1;
        }
        unsigned any = __ballot_sync(0xFFFFFFFFu, bad);
        if (lane == 0) g_mask4 = (any == 0u) ? 1 : 0;
    }
}

__global__ void k_hist(const int* __restrict__ dst) {
    int i = blockIdx.x * blockDim.x + threadIdx.x;
    if (i < NE) atomicAdd(&g_deg[dst[i]], 1);
}

// ---------------- fp32 -> fp16 row copy (feat) ------------------------------
__global__ void k_cvt(const float* __restrict__ src) {
    int i = blockIdx.x * blockDim.x + threadIdx.x;
    if (i >= NN * FD / 8) return;
    const float4* p = (const float4*)(src) + 2 * i;
    float4 a = p[0], b = p[1];
    __half2 h0 = __floats2half2_rn(a.x, a.y);
    __half2 h1 = __floats2half2_rn(a.z, a.w);
    __half2 h2 = __floats2half2_rn(b.x, b.y);
    __half2 h3 = __floats2half2_rn(b.z, b.w);
    uint4 o;
    o.x = *(uint32_t*)&h0; o.y = *(uint32_t*)&h1;
    o.z = *(uint32_t*)&h2; o.w = *(uint32_t*)&h3;
    ((uint4*)g_h16)[i] = o;
}

// ---------------- hierarchical exclusive scan -------------------------------
__global__ void __launch_bounds__(1024) k_scanA() {
    const int tid  = threadIdx.x;
    const int lane = tid & 31;
    const int wid  = tid >> 5;
    const int i    = blockIdx.x * 1024 + tid;

    int v = (i < NN) ? g_deg[i] : 0;
    int x = v;
    #pragma unroll
    for (int off = 1; off < 32; off <<= 1) {
        int y = __shfl_up_sync(0xFFFFFFFFu, x, off);
        if (lane >= off) x += y;
    }
    __shared__ int wsum[32];
    if (lane == 31) wsum[wid] = x;
    __syncthreads();
    if (wid == 0) {
        int w = wsum[lane];
        #pragma unroll
        for (int off = 1; off < 32; off <<= 1) {
            int y = __shfl_up_sync(0xFFFFFFFFu, w, off);
            if (lane >= off) w += y;
        }
        wsum[lane] = w;
    }
    __syncthreads();
    int base = (wid > 0) ? wsum[wid - 1] : 0;
    int incl = x + base;
    if (i < NN) g_start[i] = incl - v;
    if (tid == 1023) g_blockSums[blockIdx.x] = incl;
}

__global__ void k_scanC(int nblk) {
    const int t = threadIdx.x;
    const int B = (blockIdx.x * 256) >> 10;
    __shared__ int wsum[8];
    __shared__ int s_off;
    int v = (t < B) ? g_blockSums[t] : 0;
    #pragma unroll
    for (int off = 16; off > 0; off >>= 1)
        v += __shfl_down_sync(0xFFFFFFFFu, v, off);
    if ((t & 31) == 0) wsum[t >> 5] = v;
    __syncthreads();
    if (t == 0) {
        int s = 0;
        #pragma unroll
        for (int w = 0; w < 8; w++) s += wsum[w];
        s_off = s;
    }
    __syncthreads();
    int i = blockIdx.x * 256 + t;
    if (i < NN) {
        int st = g_start[i] + s_off;
        g_start[i]  = st;
        g_cursor[i] = st;
        int d = g_deg[i];
        g_invdeg[i] = 1.0f / (float)(d > 0 ? d : 1);
    }
}

__global__ void k_scatter(const int* __restrict__ src, const int* __restrict__ dst) {
    int i = blockIdx.x * blockDim.x + threadIdx.x;
    if (i < NE) {
        int d = dst[i];
        int p = atomicAdd(&g_cursor[d], 1);
        g_csr[p] = src[i];
    }
}

// ---------------- mean aggregation from fp16 rows (warp per node, MLP=4) ----
__global__ void k_agg16() {
    const __half* __restrict__ h = g_h16;
    int gw   = (blockIdx.x * blockDim.x + threadIdx.x) >> 5;
    int lane = threadIdx.x & 31;
    if (gw >= NN) return;
    int s = g_start[gw];
    int d = g_deg[gw];
    float4 acc0 = make_float4(0.f, 0.f, 0.f, 0.f);
    float4 acc1 = make_float4(0.f, 0.f, 0.f, 0.f);
    int e = 0;
    for (; e + 3 < d; e += 4) {
        int s0 = g_csr[s + e];
        int s1 = g_csr[s + e + 1];
        int s2 = g_csr[s + e + 2];
        int s3 = g_csr[s + e + 3];
        uint2 u0 = *(const uint2*)(h + (size_t)s0 * FD + lane * 4);
        uint2 u1 = *(const uint2*)(h + (size_t)s1 * FD + lane * 4);
        uint2 u2 = *(const uint2*)(h + (size_t)s2 * FD + lane * 4);
        uint2 u3 = *(const uint2*)(h + (size_t)s3 * FD + lane * 4);
        float2 a0 = __half22float2(*(__half2*)&u0.x);
        float2 a1 = __half22float2(*(__half2*)&u0.y);
        float2 b0 = __half22float2(*(__half2*)&u1.x);
        float2 b1 = __half22float2(*(__half2*)&u1.y);
        float2 c0 = __half22float2(*(__half2*)&u2.x);
        float2 c1 = __half22float2(*(__half2*)&u2.y);
        float2 d0 = __half22float2(*(__half2*)&u3.x);
        float2 d1 = __half22float2(*(__half2*)&u3.y);
        acc0.x += a0.x + b0.x; acc0.y += a0.y + b0.y;
        acc0.z += a1.x + b1.x; acc0.w += a1.y + b1.y;
        acc1.x += c0.x + d0.x; acc1.y += c0.y + d0.y;
        acc1.z += c1.x + d1.x; acc1.w += c1.y + d1.y;
    }
    for (; e < d; e++) {
        int s0 = g_csr[s + e];
        uint2 u0 = *(const uint2*)(h + (size_t)s0 * FD + lane * 4);
        float2 a0 = __half22float2(*(__half2*)&u0.x);
        float2 a1 = __half22float2(*(__half2*)&u0.y);
        acc0.x += a0.x; acc0.y += a0.y; acc0.z += a1.x; acc0.w += a1.y;
    }
    float iv = g_invdeg[gw];
    float4 r;
    r.x = (acc0.x + acc1.x) * iv;
    r.y = (acc0.y + acc1.y) * iv;
    r.z = (acc0.z + acc1.z) * iv;
    r.w = (acc0.w + acc1.w) * iv;
    *(float4*)(g_agg + (size_t)gw * FD + lane * 4) = r;
}

// ---------------- mean aggregation, 40-wide (lanes 0-9 of each warp) --------
__global__ void k_agg40() {
    const float* __restrict__ t = g_tA;
    int gw   = (blockIdx.x * blockDim.x + threadIdx.x) >> 5;
    int lane = threadIdx.x & 31;
    if (gw >= NN) return;
    int s = g_start[gw];
    int d = g_deg[gw];
    float4 acc0 = make_float4(0.f, 0.f, 0.f, 0.f);
    float4 acc1 = make_float4(0.f, 0.f, 0.f, 0.f);
    const bool act = (lane < 10);
    int e = 0;
    for (; e + 1 < d; e += 2) {
        int s0 = g_csr[s + e];
        int s1 = g_csr[s + e + 1];
        if (act) {
            float4 v0 = *(const float4*)(t + (size_t)s0 * NC + lane * 4);
            float4 v1 = *(const float4*)(t + (size_t)s1 * NC + lane * 4);
            acc0.x += v0.x; acc0.y += v0.y; acc0.z += v0.z; acc0.w += v0.w;
            acc1.x += v1.x; acc1.y += v1.y; acc1.z += v1.z; acc1.w += v1.w;
        }
    }
    if (e < d && act) {
        int s0 = g_csr[s + e];
        float4 v0 = *(const float4*)(t + (size_t)s0 * NC + lane * 4);
        acc0.x += v0.x; acc0.y += v0.y; acc0.z += v0.z; acc0.w += v0.w;
    }
    if (act) {
        float iv = g_invdeg[gw];
        float4 r;
        r.x = (acc0.x + acc1.x) * iv;
        r.y = (acc0.y + acc1.y) * iv;
        r.z = (acc0.z + acc1.z) * iv;
        r.w = (acc0.w + acc1.w) * iv;
        *(float4*)(g_t40 + (size_t)gw * NC + lane * 4) = r;
    }
}

// ---------------- final add: out = tS + t40 ---------------------------------
__global__ void k_fin(float* __restrict__ out) {
    int i = blockIdx.x * blockDim.x + threadIdx.x;
    if (i >= NN * NC / 4) return;
    float4 a = ((const float4*)g_tS)[i];
    float4 b = ((const float4*)g_t40)[i];
    float4 r;
    r.x = a.x + b.x; r.y = a.y + b.y; r.z = a.z + b.z; r.w = a.w + b.w;
    ((float4*)out)[i] = r;
}

// ---------------- TF32 tensor-core GEMM (layers 1 & 2) ----------------------
// out = relu( mask ? ([h|agg] @ [Bself;Bneigh] + bias) : gh[g2] )
// WR16=1: also store fp16 copy of the output row into g_h16.
template<int WR16>
__global__ void __launch_bounds__(256)
k_gemm_tc(int a0sel, const float* __restrict__ A0p,
          const float* __restrict__ B0, const float* __restrict__ B1,
          const float* __restrict__ bias,
          int osel,
          const void* __restrict__ maskp,
          const float* __restrict__ gh, const int* __restrict__ g2)
{
    const float* __restrict__ A0 = pick_in(a0sel, A0p);
    const float* __restrict__ A1 = g_agg;
    float* __restrict__ out = pick_out(osel, nullptr);

    __shared__ uint32_t As[128][20];
    __shared__ uint32_t Bs[16][136];

    const int tid  = threadIdx.x;
    const int lane = tid & 31;
    const int wid  = tid >> 5;
    const int row0 = blockIdx.x * 128;

    float c[16][4];
    #pragma unroll
    for (int t = 0; t < 16; t++)
        #pragma unroll
        for (int j = 0; j < 4; j++) c[t][j] = 0.f;

    const int ar = tid >> 1;
    const int ak = (tid & 1) * 8;
    const int bk = tid >> 4;
    const int bn = (tid & 15) * 8;

    #pragma unroll 1
    for (int kb = 0; kb < 16; ++kb) {
        const float* __restrict__ A = (kb >= 8) ? A1 : A0;
        const float* __restrict__ B = (kb >= 8) ? B1 : B0;
        const int kBase = (kb * 16) & 127;

        float a[8];
        const int grow = row0 + ar;
        if (grow < NN) {
            const float* p = A + (size_t)grow * 128 + kBase + ak;
            *(float4*)&a[0] = *(const float4*)(p);
            *(float4*)&a[4] = *(const float4*)(p + 4);
        } else {
            #pragma unroll
            for (int j = 0; j < 8; j++) a[j] = 0.f;
        }
        float b[8];
        {
            const float* p = B + (size_t)(kBase + bk) * 128 + bn;
            *(float4*)&b[0] = *(const float4*)(p);
            *(float4*)&b[4] = *(const float4*)(p + 4);
        }

        __syncthreads();
        {
            uint4 u0, u1;
            u0.x = f2tf(a[0]); u0.y = f2tf(a[1]); u0.z = f2tf(a[2]); u0.w = f2tf(a[3]);
            u1.x = f2tf(a[4]); u1.y = f2tf(a[5]); u1.z = f2tf(a[6]); u1.w = f2tf(a[7]);
            *(uint4*)&As[ar][ak]     = u0;
            *(uint4*)&As[ar][ak + 4] = u1;
            u0.x = f2tf(b[0]); u0.y = f2tf(b[1]); u0.z = f2tf(b[2]); u0.w = f2tf(b[3]);
            u1.x = f2tf(b[4]); u1.y = f2tf(b[5]); u1.z = f2tf(b[6]); u1.w = f2tf(b[7]);
            *(uint4*)&Bs[bk][bn]     = u0;
            *(uint4*)&Bs[bk][bn + 4] = u1;
        }
        __syncthreads();

        const int fr = wid * 16 + (lane >> 2);
        const int fc = lane & 3;
        #pragma unroll
        for (int ks = 0; ks < 2; ks++) {
            const int k0 = ks * 8;
            uint32_t a0 = As[fr][k0 + fc];
            uint32_t a1 = As[fr + 8][k0 + fc];
            uint32_t a2 = As[fr][k0 + fc + 4];
            uint32_t a3 = As[fr + 8][k0 + fc + 4];
            #pragma unroll
            for (int t = 0; t < 16; t++) {
                uint32_t b0 = Bs[k0 + fc][t * 8 + (lane >> 2)];
                uint32_t b1 = Bs[k0 + fc + 4][t * 8 + (lane >> 2)];
                mma_tf32(c[t], a0, a1, a2, a3, b0, b1);
            }
        }
    }

    const int m4 = g_mask4;
    #pragma unroll
    for (int half = 0; half < 2; half++) {
        const int r = row0 + wid * 16 + (lane >> 2) + half * 8;
        if (r >= NN) continue;
        bool mb = m4 ? (((const unsigned int*)maskp)[r] != 0u)
                     : (((const unsigned char*)maskp)[r] != 0);
        const float* gr = mb ? nullptr : (gh + (size_t)g2[r] * 128);
        #pragma unroll
        for (int t = 0; t < 16; t++) {
            const int cc = t * 8 + 2 * (lane & 3);
            float v0 = c[t][half * 2 + 0];
            float v1 = c[t][half * 2 + 1];
            float2 bv = *(const float2*)&bias[cc];
            v0 += bv.x; v1 += bv.y;
            if (!mb) {
                float2 gv = *(const float2*)&gr[cc];
                v0 = gv.x; v1 = gv.y;
            }
            v0 = fmaxf(v0, 0.f);
            v1 = fmaxf(v1, 0.f);
            float2 o; o.x = v0; o.y = v1;
            *(float2*)&out[(size_t)r * 128 + cc] = o;
            if (WR16) {
                __half2 h2 = __floats2half2_rn(v0, v1);
                *(uint32_t*)(g_h16 + (size_t)r * 128 + cc) = *(uint32_t*)&h2;
            }
        }
    }
}

// ---------------- TF32 fused layer-3 GEMM: hB @ [W3s|W3n] -------------------
// N=80 in one pass (10 m16n8 tiles). K=128 (hB only, 8 kb steps).
// cols 0..39  -> g_tS = hB@W3s + b3
// cols 40..79 -> g_tA = hB@W3n
__global__ void __launch_bounds__(256)
k_gemm_tc3(const float* __restrict__ W3s, const float* __restrict__ W3n,
           const float* __restrict__ b3)
{
    const float* __restrict__ A0 = g_hB;

    __shared__ uint32_t As[128][20];
    __shared__ uint32_t Bs[16][136];

    const int tid  = threadIdx.x;
    const int lane = tid & 31;
    const int wid  = tid >> 5;
    const int row0 = blockIdx.x * 128;

    float c[10][4];
    #pragma unroll
    for (int t = 0; t < 10; t++)
        #pragma unroll
        for (int j = 0; j < 4; j++) c[t][j] = 0.f;

    const int ar = tid >> 1;
    const int ak = (tid & 1) * 8;
    const int bk = tid >> 4;
    const int bn = (tid & 15) * 8;      // 0..120

    #pragma unroll 1
    for (int kb = 0; kb < 8; ++kb) {
        const int kBase = kb * 16;

        float a[8];
        const int grow = row0 + ar;
        if (grow < NN) {
            const float* p = A0 + (size_t)grow * 128 + kBase + ak;
            *(float4*)&a[0] = *(const float4*)(p);
            *(float4*)&a[4] = *(const float4*)(p + 4);
        } else {
            #pragma unroll
            for (int j = 0; j < 8; j++) a[j] = 0.f;
        }
        float b[8];
        {
            const int krow = kBase + bk;
            if (bn < 40) {
                const float* p = W3s + (size_t)krow * NC + bn;
                *(float4*)&b[0] = *(const float4*)(p);
                *(float4*)&b[4] = *(const float4*)(p + 4);
            } else if (bn < 80) {
                const float* p = W3n + (size_t)krow * NC + (bn - 40);
                *(float4*)&b[0] = *(const float4*)(p);
                *(float4*)&b[4] = *(const float4*)(p + 4);
            } else {
                #pragma unroll
                for (int j = 0; j < 8; j++) b[j] = 0.f;
            }
        }

        __syncthreads();
        {
            uint4 u0, u1;
            u0.x = f2tf(a[0]); u0.y = f2tf(a[1]); u0.z = f2tf(a[2]); u0.w = f2tf(a[3]);
            u1.x = f2tf(a[4]); u1.y = f2tf(a[5]); u1.z = f2tf(a[6]); u1.w = f2tf(a[7]);
            *(uint4*)&As[ar][ak]     = u0;
            *(uint4*)&As[ar][ak + 4] = u1;
            u0.x = f2tf(b[0]); u0.y = f2tf(b[1]); u0.z = f2tf(b[2]); u0.w = f2tf(b[3]);
            u1.x = f2tf(b[4]); u1.y = f2tf(b[5]); u1.z = f2tf(b[6]); u1.w = f2tf(b[7]);
            *(uint4*)&Bs[bk][bn]     = u0;
            *(uint4*)&Bs[bk][bn + 4] = u1;
        }
        __syncthreads();

        const int fr = wid * 16 + (lane >> 2);
        const int fc = lane & 3;
        #pragma unroll
        for (int ks = 0; ks < 2; ks++) {
            const int k0 = ks * 8;
            uint32_t a0 = As[fr][k0 + fc];
            uint32_t a1 = As[fr + 8][k0 + fc];
            uint32_t a2 = As[fr][k0 + fc + 4];
            uint32_t a3 = As[fr + 8][k0 + fc + 4];
            #pragma unroll
            for (int t = 0; t < 10; t++) {
                uint32_t b0 = Bs[k0 + fc][t * 8 + (lane >> 2)];
                uint32_t b1 = Bs[k0 + fc + 4][t * 8 + (lane >> 2)];
                mma_tf32(c[t], a0, a1, a2, a3, b0, b1);
            }
        }
    }

    // epilogue: t<5 -> tS (cols 0..39, +b3), t in 5..9 -> tA (cols 0..39)
    #pragma unroll
    for (int half = 0; half < 2; half++) {
        const int r = row0 + wid * 16 + (lane >> 2) + half * 8;
        if (r >= NN) continue;
        #pragma unroll
        for (int t = 0; t < 10; t++) {
            const int cc = t * 8 + 2 * (lane & 3);
            float v0 = c[t][half * 2 + 0];
            float v1 = c[t][half * 2 + 1];
            if (t < 5) {
                float2 bv = *(const float2*)&b3[cc];
                v0 += bv.x; v1 += bv.y;
                float2 o; o.x = v0; o.y = v1;
                *(float2*)&g_tS[(size_t)r * NC + cc] = o;
            } else {
                float2 o; o.x = v0; o.y = v1;
                *(float2*)&g_tA[(size_t)r * NC + (cc - 40)] = o;
            }
        }
    }
}

// ---------------- launch ----------------------------------------------------
extern "C" void kernel_launch(void* const* d_in, const int* in_sizes, int n_in,
                              void* d_out, int out_size)
{
    const float* feat = (const float*)d_in[0];
    const float* gh   = (const float*)d_in[1];
    const float* gh2  = (const float*)d_in[2];
    const float* W1s  = (const float*)d_in[3];
    const float* W1n  = (const float*)d_in[4];
    const float* b1   = (const float*)d_in[5];
    const float* W2s  = (const float*)d_in[6];
    const float* W2n  = (const float*)d_in[7];
    const float* b2   = (const float*)d_in[8];
    const float* W3s  = (const float*)d_in[9];
    const float* W3n  = (const float*)d_in[10];
    const float* b3   = (const float*)d_in[11];
    const int*   esrc = (const int*)d_in[12];
    const int*   edst = (const int*)d_in[13];
    const int*   g2   = (const int*)d_in[14];
    const void*  mask = (const void*)d_in[15];
    float* out = (float*)d_out;

    const int TB = 256;
    const int scanBlocks = (NN + 1023) / 1024;

    k_setup<<<(NN + TB - 1) / TB, TB>>>((const unsigned int*)mask);
    k_hist<<<(NE + TB - 1) / TB, TB>>>(edst);
    k_cvt<<<(NN * FD / 8 + TB - 1) / TB, TB>>>(feat);
    k_scanA<<<scanBlocks, 1024>>>();
    k_scanC<<<(NN + TB - 1) / TB, TB>>>(scanBlocks);
    k_scatter<<<(NE + TB - 1) / TB, TB>>>(esrc, edst);

    const int aggBlocks  = (NN * 32 + TB - 1) / TB;
    const int gemmBlocks = (NN + 127) / 128;

    // Layer 1: agg16(fp16 feat); GEMM writes hA + fp16 copy
    k_agg16<<<aggBlocks, TB>>>();
    k_gemm_tc<1><<<gemmBlocks, TB>>>(0, feat, W1s, W1n, b1, 1, mask, gh, g2);
    // Layer 2: agg16(fp16 hA); GEMM writes hB
    k_agg16<<<aggBlocks, TB>>>();
    k_gemm_tc<0><<<gemmBlocks, TB>>>(1, nullptr, W2s, W2n, b2, 2, mask, gh2, g2);
    // Layer 3: fused TF32 GEMM -> tS, tA; agg40(tA) -> t40; out = tS + t40
    k_gemm_tc3<<<gemmBlocks, TB>>>(W3s, W3n, b3);
    k_agg40<<<aggBlocks, TB>>>();
    k_fin<<<(NN * NC / 4 + TB - 1) / TB, TB>>>(out);
}

// round 16
// speedup vs baseline: 1.7386x; 1.0052x over previous
#include <cuda_runtime.h>
#include <cuda_bf16.h>
#include <cuda_fp16.h>
#include <stdint.h>

#define NN 100000
#define NE 1600000
#define FD 128
#define NC 40

__device__ int    g_deg[NN];
__device__ int    g_start[NN];
__device__ int    g_cursor[NN];
__device__ float  g_invdeg[NN];
__device__ int    g_csr[NE];
__device__ float  g_hA[(size_t)NN * FD];
__device__ float  g_hB[(size_t)NN * FD];
__device__ float  g_agg[(size_t)NN * FD];
__device__ __half g_h16[(size_t)NN * FD];   // fp16 gather copy (feat, then hA)
__device__ float  g_tA[(size_t)NN * NC];    // hB @ W3n
__device__ float  g_tS[(size_t)NN * NC];    // hB @ W3s + b3
__device__ int    g_mask4;
__device__ int    g_blockSums[128];

__device__ __forceinline__ const float* pick_in(int sel, const float* p) {
    if (sel == 1) return g_hA;
    if (sel == 2) return g_hB;
    return p;
}
__device__ __forceinline__ float* pick_out(int sel, float* p) {
    if (sel == 1) return g_hA;
    if (sel == 2) return g_hB;
    return p;
}

__device__ __forceinline__ uint32_t f2tf(float f) {
    uint32_t r;
    asm("cvt.rna.tf32.f32 %0, %1;" : "=r"(r) : "f"(f));
    return r;
}
__device__ __forceinline__ void mma_tf32(float* c,
                                         uint32_t a0, uint32_t a1,
                                         uint32_t a2, uint32_t a3,
                                         uint32_t b0, uint32_t b1) {
    asm("mma.sync.aligned.m16n8k8.row.col.f32.tf32.tf32.f32 "
        "{%0,%1,%2,%3}, {%4,%5,%6,%7}, {%8,%9}, {%0,%1,%2,%3};"
        : "+f"(c[0]), "+f"(c[1]), "+f"(c[2]), "+f"(c[3])
        : "r"(a0), "r"(a1), "r"(a2), "r"(a3), "r"(b0), "r"(b1));
}

// ---------------- setup: zero deg + fp16 convert + mask dtype probe ---------
// grid covers NN*FD/8 (cvt work); deg-zero and probe ride along.
__global__ void k_setup(const float* __restrict__ feat,
                        const unsigned int* __restrict__ m) {
    int i = blockIdx.x * blockDim.x + threadIdx.x;
    if (i < NN * FD / 8) {
        const float4* p = (const float4*)(feat) + 2 * i;
        float4 a = p[0], b = p[1];
        __half2 h0 = __floats2half2_rn(a.x, a.y);
        __half2 h1 = __floats2half2_rn(a.z, a.w);
        __half2 h2 = __floats2half2_rn(b.x, b.y);
        __half2 h3 = __floats2half2_rn(b.z, b.w);
        uint4 o;
        o.x = *(uint32_t*)&h0; o.y = *(uint32_t*)&h1;
        o.z = *(uint32_t*)&h2; o.w = *(uint32_t*)&h3;
        ((uint4*)g_h16)[i] = o;
    }
    if (i < NN) g_deg[i] = 0;
    if (blockIdx.x == 0 && threadIdx.x < 32) {
        int lane = threadIdx.x;
        unsigned bad = 0;
        for (int j = lane; j < 64; j += 32) {
            unsigned v = m[j];
            if (!(v == 0u || v == 1u || v == 0x3F800000u)) bad = 1;
        }
        unsigned any = __ballot_sync(0xFFFFFFFFu, bad);
        if (lane == 0) g_mask4 = (any == 0u) ? 1 : 0;
    }
}

__global__ void k_hist(const int* __restrict__ dst) {
    int i = blockIdx.x * blockDim.x + threadIdx.x;
    if (i < NE) atomicAdd(&g_deg[dst[i]], 1);
}

// ---------------- hierarchical exclusive scan -------------------------------
__global__ void __launch_bounds__(1024) k_scanA() {
    const int tid  = threadIdx.x;
    const int lane = tid & 31;
    const int wid  = tid >> 5;
    const int i    = blockIdx.x * 1024 + tid;

    int v = (i < NN) ? g_deg[i] : 0;
    int x = v;
    #pragma unroll
    for (int off = 1; off < 32; off <<= 1) {
        int y = __shfl_up_sync(0xFFFFFFFFu, x, off);
        if (lane >= off) x += y;
    }
    __shared__ int wsum[32];
    if (lane == 31) wsum[wid] = x;
    __syncthreads();
    if (wid == 0) {
        int w = wsum[lane];
        #pragma unroll
        for (int off = 1; off < 32; off <<= 1) {
            int y = __shfl_up_sync(0xFFFFFFFFu, w, off);
            if (lane >= off) w += y;
        }
        wsum[lane] = w;
    }
    __syncthreads();
    int base = (wid > 0) ? wsum[wid - 1] : 0;
    int incl = x + base;
    if (i < NN) g_start[i] = incl - v;
    if (tid == 1023) g_blockSums[blockIdx.x] = incl;
}

__global__ void k_scanC(int nblk) {
    const int t = threadIdx.x;
    const int B = (blockIdx.x * 256) >> 10;
    __shared__ int wsum[8];
    __shared__ int s_off;
    int v = (t < B) ? g_blockSums[t] : 0;
    #pragma unroll
    for (int off = 16; off > 0; off >>= 1)
        v += __shfl_down_sync(0xFFFFFFFFu, v, off);
    if ((t & 31) == 0) wsum[t >> 5] = v;
    __syncthreads();
    if (t == 0) {
        int s = 0;
        #pragma unroll
        for (int w = 0; w < 8; w++) s += wsum[w];
        s_off = s;
    }
    __syncthreads();
    int i = blockIdx.x * 256 + t;
    if (i < NN) {
        int st = g_start[i] + s_off;
        g_start[i]  = st;
        g_cursor[i] = st;
        int d = g_deg[i];
        g_invdeg[i] = 1.0f / (float)(d > 0 ? d : 1);
    }
}

__global__ void k_scatter(const int* __restrict__ src, const int* __restrict__ dst) {
    int i = blockIdx.x * blockDim.x + threadIdx.x;
    if (i < NE) {
        int d = dst[i];
        int p = atomicAdd(&g_cursor[d], 1);
        g_csr[p] = src[i];
    }
}

// ---------------- mean aggregation from fp16 rows (warp per node, MLP=4) ----
__global__ void k_agg16() {
    const __half* __restrict__ h = g_h16;
    int gw   = (blockIdx.x * blockDim.x + threadIdx.x) >> 5;
    int lane = threadIdx.x & 31;
    if (gw >= NN) return;
    int s = g_start[gw];
    int d = g_deg[gw];
    float4 acc0 = make_float4(0.f, 0.f, 0.f, 0.f);
    float4 acc1 = make_float4(0.f, 0.f, 0.f, 0.f);
    int e = 0;
    for (; e + 3 < d; e += 4) {
        int s0 = g_csr[s + e];
        int s1 = g_csr[s + e + 1];
        int s2 = g_csr[s + e + 2];
        int s3 = g_csr[s + e + 3];
        uint2 u0 = *(const uint2*)(h + (size_t)s0 * FD + lane * 4);
        uint2 u1 = *(const uint2*)(h + (size_t)s1 * FD + lane * 4);
        uint2 u2 = *(const uint2*)(h + (size_t)s2 * FD + lane * 4);
        uint2 u3 = *(const uint2*)(h + (size_t)s3 * FD + lane * 4);
        float2 a0 = __half22float2(*(__half2*)&u0.x);
        float2 a1 = __half22float2(*(__half2*)&u0.y);
        float2 b0 = __half22float2(*(__half2*)&u1.x);
        float2 b1 = __half22float2(*(__half2*)&u1.y);
        float2 c0 = __half22float2(*(__half2*)&u2.x);
        float2 c1 = __half22float2(*(__half2*)&u2.y);
        float2 d0 = __half22float2(*(__half2*)&u3.x);
        float2 d1 = __half22float2(*(__half2*)&u3.y);
        acc0.x += a0.x + b0.x; acc0.y += a0.y + b0.y;
        acc0.z += a1.x + b1.x; acc0.w += a1.y + b1.y;
        acc1.x += c0.x + d0.x; acc1.y += c0.y + d0.y;
        acc1.z += c1.x + d1.x; acc1.w += c1.y + d1.y;
    }
    for (; e < d; e++) {
        int s0 = g_csr[s + e];
        uint2 u0 = *(const uint2*)(h + (size_t)s0 * FD + lane * 4);
        float2 a0 = __half22float2(*(__half2*)&u0.x);
        float2 a1 = __half22float2(*(__half2*)&u0.y);
        acc0.x += a0.x; acc0.y += a0.y; acc0.z += a1.x; acc0.w += a1.y;
    }
    float iv = g_invdeg[gw];
    float4 r;
    r.x = (acc0.x + acc1.x) * iv;
    r.y = (acc0.y + acc1.y) * iv;
    r.z = (acc0.z + acc1.z) * iv;
    r.w = (acc0.w + acc1.w) * iv;
    *(float4*)(g_agg + (size_t)gw * FD + lane * 4) = r;
}

// ---------------- layer-3 finish: out = tS + mean(tA over neighbors) --------
// warp per node, lanes 0-9 active (40 floats). Fused former k_fin.
__global__ void k_agg40(float* __restrict__ out) {
    const float* __restrict__ t = g_tA;
    int gw   = (blockIdx.x * blockDim.x + threadIdx.x) >> 5;
    int lane = threadIdx.x & 31;
    if (gw >= NN) return;
    int s = g_start[gw];
    int d = g_deg[gw];
    float4 acc0 = make_float4(0.f, 0.f, 0.f, 0.f);
    float4 acc1 = make_float4(0.f, 0.f, 0.f, 0.f);
    const bool act = (lane < 10);
    int e = 0;
    for (; e + 1 < d; e += 2) {
        int s0 = g_csr[s + e];
        int s1 = g_csr[s + e + 1];
        if (act) {
            float4 v0 = *(const float4*)(t + (size_t)s0 * NC + lane * 4);
            float4 v1 = *(const float4*)(t + (size_t)s1 * NC + lane * 4);
            acc0.x += v0.x; acc0.y += v0.y; acc0.z += v0.z; acc0.w += v0.w;
            acc1.x += v1.x; acc1.y += v1.y; acc1.z += v1.z; acc1.w += v1.w;
        }
    }
    if (e < d && act) {
        int s0 = g_csr[s + e];
        float4 v0 = *(const float4*)(t + (size_t)s0 * NC + lane * 4);
        acc0.x += v0.x; acc0.y += v0.y; acc0.z += v0.z; acc0.w += v0.w;
    }
    if (act) {
        float iv = g_invdeg[gw];
        float4 ts = *(const float4*)(g_tS + (size_t)gw * NC + lane * 4);
        float4 r;
        r.x = ts.x + (acc0.x + acc1.x) * iv;
        r.y = ts.y + (acc0.y + acc1.y) * iv;
        r.z = ts.z + (acc0.z + acc1.z) * iv;
        r.w = ts.w + (acc0.w + acc1.w) * iv;
        *(float4*)(out + (size_t)gw * NC + lane * 4) = r;
    }
}

// ---------------- TF32 tensor-core GEMM (layers 1 & 2) ----------------------
// out = relu( mask ? ([h|agg] @ [Bself;Bneigh] + bias) : gh[g2] )
// WR16=1: also store fp16 copy of the output row into g_h16.
template<int WR16>
__global__ void __launch_bounds__(256)
k_gemm_tc(int a0sel, const float* __restrict__ A0p,
          const float* __restrict__ B0, const float* __restrict__ B1,
          const float* __restrict__ bias,
          int osel,
          const void* __restrict__ maskp,
          const float* __restrict__ gh, const int* __restrict__ g2)
{
    const float* __restrict__ A0 = pick_in(a0sel, A0p);
    const float* __restrict__ A1 = g_agg;
    float* __restrict__ out = pick_out(osel, nullptr);

    __shared__ uint32_t As[128][20];
    __shared__ uint32_t Bs[16][136];

    const int tid  = threadIdx.x;
    const int lane = tid & 31;
    const int wid  = tid >> 5;
    const int row0 = blockIdx.x * 128;

    float c[16][4];
    #pragma unroll
    for (int t = 0; t < 16; t++)
        #pragma unroll
        for (int j = 0; j < 4; j++) c[t][j] = 0.f;

    const int ar = tid >> 1;
    const int ak = (tid & 1) * 8;
    const int bk = tid >> 4;
    const int bn = (tid & 15) * 8;

    #pragma unroll 1
    for (int kb = 0; kb < 16; ++kb) {
        const float* __restrict__ A = (kb >= 8) ? A1 : A0;
        const float* __restrict__ B = (kb >= 8) ? B1 : B0;
        const int kBase = (kb * 16) & 127;

        float a[8];
        const int grow = row0 + ar;
        if (grow < NN) {
            const float* p = A + (size_t)grow * 128 + kBase + ak;
            *(float4*)&a[0] = *(const float4*)(p);
            *(float4*)&a[4] = *(const float4*)(p + 4);
        } else {
            #pragma unroll
            for (int j = 0; j < 8; j++) a[j] = 0.f;
        }
        float b[8];
        {
            const float* p = B + (size_t)(kBase + bk) * 128 + bn;
            *(float4*)&b[0] = *(const float4*)(p);
            *(float4*)&b[4] = *(const float4*)(p + 4);
        }

        __syncthreads();
        {
            uint4 u0, u1;
            u0.x = f2tf(a[0]); u0.y = f2tf(a[1]); u0.z = f2tf(a[2]); u0.w = f2tf(a[3]);
            u1.x = f2tf(a[4]); u1.y = f2tf(a[5]); u1.z = f2tf(a[6]); u1.w = f2tf(a[7]);
            *(uint4*)&As[ar][ak]     = u0;
            *(uint4*)&As[ar][ak + 4] = u1;
            u0.x = f2tf(b[0]); u0.y = f2tf(b[1]); u0.z = f2tf(b[2]); u0.w = f2tf(b[3]);
            u1.x = f2tf(b[4]); u1.y = f2tf(b[5]); u1.z = f2tf(b[6]); u1.w = f2tf(b[7]);
            *(uint4*)&Bs[bk][bn]     = u0;
            *(uint4*)&Bs[bk][bn + 4] = u1;
        }
        __syncthreads();

        const int fr = wid * 16 + (lane >> 2);
        const int fc = lane & 3;
        #pragma unroll
        for (int ks = 0; ks < 2; ks++) {
            const int k0 = ks * 8;
            uint32_t a0 = As[fr][k0 + fc];
            uint32_t a1 = As[fr + 8][k0 + fc];
            uint32_t a2 = As[fr][k0 + fc + 4];
            uint32_t a3 = As[fr + 8][k0 + fc + 4];
            #pragma unroll
            for (int t = 0; t < 16; t++) {
                uint32_t b0 = Bs[k0 + fc][t * 8 + (lane >> 2)];
                uint32_t b1 = Bs[k0 + fc + 4][t * 8 + (lane >> 2)];
                mma_tf32(c[t], a0, a1, a2, a3, b0, b1);
            }
        }
    }

    const int m4 = g_mask4;
    #pragma unroll
    for (int half = 0; half < 2; half++) {
        const int r = row0 + wid * 16 + (lane >> 2) + half * 8;
        if (r >= NN) continue;
        bool mb = m4 ? (((const unsigned int*)maskp)[r] != 0u)
                     : (((const unsigned char*)maskp)[r] != 0);
        const float* gr = mb ? nullptr : (gh + (size_t)g2[r] * 128);
        #pragma unroll
        for (int t = 0; t < 16; t++) {
            const int cc = t * 8 + 2 * (lane & 3);
            float v0 = c[t][half * 2 + 0];
            float v1 = c[t][half * 2 + 1];
            float2 bv = *(const float2*)&bias[cc];
            v0 += bv.x; v1 += bv.y;
            if (!mb) {
                float2 gv = *(const float2*)&gr[cc];
                v0 = gv.x; v1 = gv.y;
            }
            v0 = fmaxf(v0, 0.f);
            v1 = fmaxf(v1, 0.f);
            float2 o; o.x = v0; o.y = v1;
            *(float2*)&out[(size_t)r * 128 + cc] = o;
            if (WR16) {
                __half2 h2 = __floats2half2_rn(v0, v1);
                *(uint32_t*)(g_h16 + (size_t)r * 128 + cc) = *(uint32_t*)&h2;
            }
        }
    }
}

// ---------------- TF32 fused layer-3 GEMM: hB @ [W3s|W3n] -------------------
// N=80 in one pass (10 m16n8 tiles). K=128 (hB only, 8 kb steps).
// cols 0..39  -> g_tS = hB@W3s + b3
// cols 40..79 -> g_tA = hB@W3n
__global__ void __launch_bounds__(256)
k_gemm_tc3(const float* __restrict__ W3s, const float* __restrict__ W3n,
           const float* __restrict__ b3)
{
    const float* __restrict__ A0 = g_hB;

    __shared__ uint32_t As[128][20];
    __shared__ uint32_t Bs[16][136];

    const int tid  = threadIdx.x;
    const int lane = tid & 31;
    const int wid  = tid >> 5;
    const int row0 = blockIdx.x * 128;

    float c[10][4];
    #pragma unroll
    for (int t = 0; t < 10; t++)
        #pragma unroll
        for (int j = 0; j < 4; j++) c[t][j] = 0.f;

    const int ar = tid >> 1;
    const int ak = (tid & 1) * 8;
    const int bk = tid >> 4;
    const int bn = (tid & 15) * 8;

    #pragma unroll 1
    for (int kb = 0; kb < 8; ++kb) {
        const int kBase = kb * 16;

        float a[8];
        const int grow = row0 + ar;
        if (grow < NN) {
            const float* p = A0 + (size_t)grow * 128 + kBase + ak;
            *(float4*)&a[0] = *(const float4*)(p);
            *(float4*)&a[4] = *(const float4*)(p + 4);
        } else {
            #pragma unroll
            for (int j = 0; j < 8; j++) a[j] = 0.f;
        }
        float b[8];
        {
            const int krow = kBase + bk;
            if (bn < 40) {
                const float* p = W3s + (size_t)krow * NC + bn;
                *(float4*)&b[0] = *(const float4*)(p);
                *(float4*)&b[4] = *(const float4*)(p + 4);
            } else if (bn < 80) {
                const float* p = W3n + (size_t)krow * NC + (bn - 40);
                *(float4*)&b[0] = *(const float4*)(p);
                *(float4*)&b[4] = *(const float4*)(p + 4);
            } else {
                #pragma unroll
                for (int j = 0; j < 8; j++) b[j] = 0.f;
            }
        }

        __syncthreads();
        {
            uint4 u0, u1;
            u0.x = f2tf(a[0]); u0.y = f2tf(a[1]); u0.z = f2tf(a[2]); u0.w = f2tf(a[3]);
            u1.x = f2tf(a[4]); u1.y = f2tf(a[5]); u1.z = f2tf(a[6]); u1.w = f2tf(a[7]);
            *(uint4*)&As[ar][ak]     = u0;
            *(uint4*)&As[ar][ak + 4] = u1;
            u0.x = f2tf(b[0]); u0.y = f2tf(b[1]); u0.z = f2tf(b[2]); u0.w = f2tf(b[3]);
            u1.x = f2tf(b[4]); u1.y = f2tf(b[5]); u1.z = f2tf(b[6]); u1.w = f2tf(b[7]);
            *(uint4*)&Bs[bk][bn]     = u0;
            *(uint4*)&Bs[bk][bn + 4] = u1;
        }
        __syncthreads();

        const int fr = wid * 16 + (lane >> 2);
        const int fc = lane & 3;
        #pragma unroll
        for (int ks = 0; ks < 2; ks++) {
            const int k0 = ks * 8;
            uint32_t a0 = As[fr][k0 + fc];
            uint32_t a1 = As[fr + 8][k0 + fc];
            uint32_t a2 = As[fr][k0 + fc + 4];
            uint32_t a3 = As[fr + 8][k0 + fc + 4];
            #pragma unroll
            for (int t = 0; t < 10; t++) {
                uint32_t b0 = Bs[k0 + fc][t * 8 + (lane >> 2)];
                uint32_t b1 = Bs[k0 + fc + 4][t * 8 + (lane >> 2)];
                mma_tf32(c[t], a0, a1, a2, a3, b0, b1);
            }
        }
    }

    #pragma unroll
    for (int half = 0; half < 2; half++) {
        const int r = row0 + wid * 16 + (lane >> 2) + half * 8;
        if (r >= NN) continue;
        #pragma unroll
        for (int t = 0; t < 10; t++) {
            const int cc = t * 8 + 2 * (lane & 3);
            float v0 = c[t][half * 2 + 0];
            float v1 = c[t][half * 2 + 1];
            if (t < 5) {
                float2 bv = *(const float2*)&b3[cc];
                v0 += bv.x; v1 += bv.y;
                float2 o; o.x = v0; o.y = v1;
                *(float2*)&g_tS[(size_t)r * NC + cc] = o;
            } else {
                float2 o; o.x = v0; o.y = v1;
                *(float2*)&g_tA[(size_t)r * NC + (cc - 40)] = o;
            }
        }
    }
}

// ---------------- launch ----------------------------------------------------
extern "C" void kernel_launch(void* const* d_in, const int* in_sizes, int n_in,
                              void* d_out, int out_size)
{
    const float* feat = (const float*)d_in[0];
    const float* gh   = (const float*)d_in[1];
    const float* gh2  = (const float*)d_in[2];
    const float* W1s  = (const float*)d_in[3];
    const float* W1n  = (const float*)d_in[4];
    const float* b1   = (const float*)d_in[5];
    const float* W2s  = (const float*)d_in[6];
    const float* W2n  = (const float*)d_in[7];
    const float* b2   = (const float*)d_in[8];
    const float* W3s  = (const float*)d_in[9];
    const float* W3n  = (const float*)d_in[10];
    const float* b3   = (const float*)d_in[11];
    const int*   esrc = (const int*)d_in[12];
    const int*   edst = (const int*)d_in[13];
    const int*   g2   = (const int*)d_in[14];
    const void*  mask = (const void*)d_in[15];
    float* out = (float*)d_out;

    const int TB = 256;
    const int scanBlocks = (NN + 1023) / 1024;
    const int aggBlocks  = (NN * 32 + TB - 1) / TB;
    const int gemmBlocks = (NN + 127) / 128;

    // CSR build + fp16 convert (cvt folded into setup)
    k_setup<<<(NN * FD / 8 + TB - 1) / TB, TB>>>(feat, (const unsigned int*)mask);
    k_hist<<<(NE + TB - 1) / TB, TB>>>(edst);
    k_scanA<<<scanBlocks, 1024>>>();
    k_scanC<<<(NN + TB - 1) / TB, TB>>>(scanBlocks);
    k_scatter<<<(NE + TB - 1) / TB, TB>>>(esrc, edst);

    // Layer 1: agg16(fp16 feat) [6th launch -> ncu window]; GEMM -> hA + fp16
    k_agg16<<<aggBlocks, TB>>>();
    k_gemm_tc<1><<<gemmBlocks, TB>>>(0, feat, W1s, W1n, b1, 1, mask, gh, g2);
    // Layer 2: agg16(fp16 hA); GEMM -> hB
    k_agg16<<<aggBlocks, TB>>>();
    k_gemm_tc<0><<<gemmBlocks, TB>>>(1, nullptr, W2s, W2n, b2, 2, mask, gh2, g2);
    // Layer 3: fused TF32 GEMM -> tS, tA; agg40 adds tS and writes out
    k_gemm_tc3<<<gemmBlocks, TB>>>(W3s, W3n, b3);
    k_agg40<<<aggBlocks, TB>>>(out);
}

// round 17
// speedup vs baseline: 2.1986x; 1.2646x over previous
#include <cuda_runtime.h>
#include <cuda_bf16.h>
#include <cuda_fp16.h>
#include <stdint.h>

#define NN 100000
#define NE 1600000
#define FD 128
#define NC 40

__device__ int    g_deg[NN];
__device__ int    g_start[NN];
__device__ int    g_cursor[NN];
__device__ float  g_invdeg[NN];
__device__ int    g_csr[NE];
__device__ float  g_agg[(size_t)NN * FD];
__device__ __half g_h16[(size_t)NN * FD];   // fp16 activations (feat -> hA -> hB)
__device__ float  g_tA[(size_t)NN * NC];    // hB @ W3n
__device__ float  g_tS[(size_t)NN * NC];    // hB @ W3s + b3
__device__ int    g_mask4;
__device__ int    g_blockSums[128];

// ---------------- helpers ---------------------------------------------------
__device__ __forceinline__ void mma_f16(float* c,
                                        uint32_t a0, uint32_t a1,
                                        uint32_t a2, uint32_t a3,
                                        uint32_t b0, uint32_t b1) {
    asm("mma.sync.aligned.m16n8k16.row.col.f32.f16.f16.f32 "
        "{%0,%1,%2,%3}, {%4,%5,%6,%7}, {%8,%9}, {%0,%1,%2,%3};"
        : "+f"(c[0]), "+f"(c[1]), "+f"(c[2]), "+f"(c[3])
        : "r"(a0), "r"(a1), "r"(a2), "r"(a3), "r"(b0), "r"(b1));
}
__device__ __forceinline__ uint32_t pack_h2(float lo, float hi) {
    __half2 h = __floats2half2_rn(lo, hi);
    return *(uint32_t*)&h;
}

// ---------------- setup: zero deg + fp16 convert + mask dtype probe ---------
__global__ void k_setup(const float* __restrict__ feat,
                        const unsigned int* __restrict__ m) {
    int i = blockIdx.x * blockDim.x + threadIdx.x;
    if (i < NN * FD / 8) {
        const float4* p = (const float4*)(feat) + 2 * i;
        float4 a = p[0], b = p[1];
        uint4 o;
        o.x = pack_h2(a.x, a.y); o.y = pack_h2(a.z, a.w);
        o.z = pack_h2(b.x, b.y); o.w = pack_h2(b.z, b.w);
        ((uint4*)g_h16)[i] = o;
    }
    if (i < NN) g_deg[i] = 0;
    if (blockIdx.x == 0 && threadIdx.x < 32) {
        int lane = threadIdx.x;
        unsigned bad = 0;
        for (int j = lane; j < 64; j += 32) {
            unsigned v = m[j];
            if (!(v == 0u || v == 1u || v == 0x3F800000u)) bad = 1;
        }
        unsigned any = __ballot_sync(0xFFFFFFFFu, bad);
        if (lane == 0) g_mask4 = (any == 0u) ? 1 : 0;
    }
}

__global__ void k_hist(const int* __restrict__ dst) {
    int i = blockIdx.x * blockDim.x + threadIdx.x;
    if (i < NE) atomicAdd(&g_deg[dst[i]], 1);
}

// ---------------- hierarchical exclusive scan -------------------------------
__global__ void __launch_bounds__(1024) k_scanA() {
    const int tid  = threadIdx.x;
    const int lane = tid & 31;
    const int wid  = tid >> 5;
    const int i    = blockIdx.x * 1024 + tid;

    int v = (i < NN) ? g_deg[i] : 0;
    int x = v;
    #pragma unroll
    for (int off = 1; off < 32; off <<= 1) {
        int y = __shfl_up_sync(0xFFFFFFFFu, x, off);
        if (lane >= off) x += y;
    }
    __shared__ int wsum[32];
    if (lane == 31) wsum[wid] = x;
    __syncthreads();
    if (wid == 0) {
        int w = wsum[lane];
        #pragma unroll
        for (int off = 1; off < 32; off <<= 1) {
            int y = __shfl_up_sync(0xFFFFFFFFu, w, off);
            if (lane >= off) w += y;
        }
        wsum[lane] = w;
    }
    __syncthreads();
    int base = (wid > 0) ? wsum[wid - 1] : 0;
    int incl = x + base;
    if (i < NN) g_start[i] = incl - v;
    if (tid == 1023) g_blockSums[blockIdx.x] = incl;
}

__global__ void k_scanC(int nblk) {
    const int t = threadIdx.x;
    const int B = (blockIdx.x * 256) >> 10;
    __shared__ int wsum[8];
    __shared__ int s_off;
    int v = (t < B) ? g_blockSums[t] : 0;
    #pragma unroll
    for (int off = 16; off > 0; off >>= 1)
        v += __shfl_down_sync(0xFFFFFFFFu, v, off);
    if ((t & 31) == 0) wsum[t >> 5] = v;
    __syncthreads();
    if (t == 0) {
        int s = 0;
        #pragma unroll
        for (int w = 0; w < 8; w++) s += wsum[w];
        s_off = s;
    }
    __syncthreads();
    int i = blockIdx.x * 256 + t;
    if (i < NN) {
        int st = g_start[i] + s_off;
        g_start[i]  = st;
        g_cursor[i] = st;
        int d = g_deg[i];
        g_invdeg[i] = 1.0f / (float)(d > 0 ? d : 1);
    }
}

__global__ void k_scatter(const int* __restrict__ src, const int* __restrict__ dst) {
    int i = blockIdx.x * blockDim.x + threadIdx.x;
    if (i < NE) {
        int d = dst[i];
        int p = atomicAdd(&g_cursor[d], 1);
        g_csr[p] = src[i];
    }
}

// ---------------- mean aggregation from fp16 rows (warp per node, MLP=4) ----
__global__ void k_agg16() {
    const __half* __restrict__ h = g_h16;
    int gw   = (blockIdx.x * blockDim.x + threadIdx.x) >> 5;
    int lane = threadIdx.x & 31;
    if (gw >= NN) return;
    int s = g_start[gw];
    int d = g_deg[gw];
    float4 acc0 = make_float4(0.f, 0.f, 0.f, 0.f);
    float4 acc1 = make_float4(0.f, 0.f, 0.f, 0.f);
    int e = 0;
    for (; e + 3 < d; e += 4) {
        int s0 = g_csr[s + e];
        int s1 = g_csr[s + e + 1];
        int s2 = g_csr[s + e + 2];
        int s3 = g_csr[s + e + 3];
        uint2 u0 = *(const uint2*)(h + (size_t)s0 * FD + lane * 4);
        uint2 u1 = *(const uint2*)(h + (size_t)s1 * FD + lane * 4);
        uint2 u2 = *(const uint2*)(h + (size_t)s2 * FD + lane * 4);
        uint2 u3 = *(const uint2*)(h + (size_t)s3 * FD + lane * 4);
        float2 a0 = __half22float2(*(__half2*)&u0.x);
        float2 a1 = __half22float2(*(__half2*)&u0.y);
        float2 b0 = __half22float2(*(__half2*)&u1.x);
        float2 b1 = __half22float2(*(__half2*)&u1.y);
        float2 c0 = __half22float2(*(__half2*)&u2.x);
        float2 c1 = __half22float2(*(__half2*)&u2.y);
        float2 d0 = __half22float2(*(__half2*)&u3.x);
        float2 d1 = __half22float2(*(__half2*)&u3.y);
        acc0.x += a0.x + b0.x; acc0.y += a0.y + b0.y;
        acc0.z += a1.x + b1.x; acc0.w += a1.y + b1.y;
        acc1.x += c0.x + d0.x; acc1.y += c0.y + d0.y;
        acc1.z += c1.x + d1.x; acc1.w += c1.y + d1.y;
    }
    for (; e < d; e++) {
        int s0 = g_csr[s + e];
        uint2 u0 = *(const uint2*)(h + (size_t)s0 * FD + lane * 4);
        float2 a0 = __half22float2(*(__half2*)&u0.x);
        float2 a1 = __half22float2(*(__half2*)&u0.y);
        acc0.x += a0.x; acc0.y += a0.y; acc0.z += a1.x; acc0.w += a1.y;
    }
    float iv = g_invdeg[gw];
    float4 r;
    r.x = (acc0.x + acc1.x) * iv;
    r.y = (acc0.y + acc1.y) * iv;
    r.z = (acc0.z + acc1.z) * iv;
    r.w = (acc0.w + acc1.w) * iv;
    *(float4*)(g_agg + (size_t)gw * FD + lane * 4) = r;
}

// ---------------- layer-3 finish: out = tS + mean(tA over neighbors) --------
__global__ void k_agg40(float* __restrict__ out) {
    const float* __restrict__ t = g_tA;
    int gw   = (blockIdx.x * blockDim.x + threadIdx.x) >> 5;
    int lane = threadIdx.x & 31;
    if (gw >= NN) return;
    int s = g_start[gw];
    int d = g_deg[gw];
    float4 acc0 = make_float4(0.f, 0.f, 0.f, 0.f);
    float4 acc1 = make_float4(0.f, 0.f, 0.f, 0.f);
    const bool act = (lane < 10);
    int e = 0;
    for (; e + 1 < d; e += 2) {
        int s0 = g_csr[s + e];
        int s1 = g_csr[s + e + 1];
        if (act) {
            float4 v0 = *(const float4*)(t + (size_t)s0 * NC + lane * 4);
            float4 v1 = *(const float4*)(t + (size_t)s1 * NC + lane * 4);
            acc0.x += v0.x; acc0.y += v0.y; acc0.z += v0.z; acc0.w += v0.w;
            acc1.x += v1.x; acc1.y += v1.y; acc1.z += v1.z; acc1.w += v1.w;
        }
    }
    if (e < d && act) {
        int s0 = g_csr[s + e];
        float4 v0 = *(const float4*)(t + (size_t)s0 * NC + lane * 4);
        acc0.x += v0.x; acc0.y += v0.y; acc0.z += v0.z; acc0.w += v0.w;
    }
    if (act) {
        float iv = g_invdeg[gw];
        float4 ts = *(const float4*)(g_tS + (size_t)gw * NC + lane * 4);
        float4 r;
        r.x = ts.x + (acc0.x + acc1.x) * iv;
        r.y = ts.y + (acc0.y + acc1.y) * iv;
        r.z = ts.z + (acc0.z + acc1.z) * iv;
        r.w = ts.w + (acc0.w + acc1.w) * iv;
        *(float4*)(out + (size_t)gw * NC + lane * 4) = r;
    }
}

// ---------------- fp16 tensor-core GEMM (layers 1 & 2) ----------------------
// next_h16 = relu( mask ? ([h16|agg] @ [Bself;Bneigh] + bias) : gh[g2] )
// A low half from g_h16 (fp16), high half from g_agg (fp32, converted).
// Output written ONLY as fp16 into g_h16 (all consumers read fp16 now).
// m16n8k16: As16 half2 words stride 12 (conflict-free), Bs16 [8][136] half2.
__global__ void __launch_bounds__(256)
k_gemm_hc(const float* __restrict__ B0, const float* __restrict__ B1,
          const float* __restrict__ bias,
          const void* __restrict__ maskp,
          const float* __restrict__ gh, const int* __restrict__ g2)
{
    __shared__ uint32_t As16[128][12];   // half2 words, cols 0..7 used
    __shared__ uint32_t Bs16[8][136];    // half2 words (k-pair, col)

    const int tid  = threadIdx.x;
    const int lane = tid & 31;
    const int wid  = tid >> 5;
    const int row0 = blockIdx.x * 128;

    float c[16][4];
    #pragma unroll
    for (int t = 0; t < 16; t++)
        #pragma unroll
        for (int j = 0; j < 4; j++) c[t][j] = 0.f;

    const int ar = tid >> 1;            // A stage row 0..127
    const int aw = (tid & 1) * 4;       // A word offset 0/4 (k offset 0/8)
    const int bk2 = tid >> 5;           // B k-pair 0..7
    const int bc  = (tid & 31) * 4;     // B col 0..124

    #pragma unroll 1
    for (int kb = 0; kb < 16; ++kb) {
        const int kBase = (kb & 7) * 16;

        // stage A fragment: 4 half2 words
        uint4 av;
        const int grow = row0 + ar;
        if (grow < NN) {
            if (kb < 8) {
                av = *(const uint4*)(g_h16 + (size_t)grow * FD + kBase + aw * 2);
            } else {
                const float* p = g_agg + (size_t)grow * FD + kBase + aw * 2;
                float4 f0 = *(const float4*)(p);
                float4 f1 = *(const float4*)(p + 4);
                av.x = pack_h2(f0.x, f0.y); av.y = pack_h2(f0.z, f0.w);
                av.z = pack_h2(f1.x, f1.y); av.w = pack_h2(f1.z, f1.w);
            }
        } else {
            av = make_uint4(0u, 0u, 0u, 0u);
        }
        // stage B fragment: pack rows 2k2, 2k2+1
        const float* __restrict__ W = (kb < 8) ? B0 : B1;
        float4 r0 = *(const float4*)(W + (size_t)(kBase + 2 * bk2) * FD + bc);
        float4 r1 = *(const float4*)(W + (size_t)(kBase + 2 * bk2 + 1) * FD + bc);

        __syncthreads();
        As16[ar][aw + 0] = av.x; As16[ar][aw + 1] = av.y;
        As16[ar][aw + 2] = av.z; As16[ar][aw + 3] = av.w;
        Bs16[bk2][bc + 0] = pack_h2(r0.x, r1.x);
        Bs16[bk2][bc + 1] = pack_h2(r0.y, r1.y);
        Bs16[bk2][bc + 2] = pack_h2(r0.z, r1.z);
        Bs16[bk2][bc + 3] = pack_h2(r0.w, r1.w);
        __syncthreads();

        const int fr = wid * 16 + (lane >> 2);
        const int fc = lane & 3;
        uint32_t a0 = As16[fr][fc];
        uint32_t a1 = As16[fr + 8][fc];
        uint32_t a2 = As16[fr][fc + 4];
        uint32_t a3 = As16[fr + 8][fc + 4];
        #pragma unroll
        for (int t = 0; t < 16; t++) {
            uint32_t b0 = Bs16[fc][t * 8 + (lane >> 2)];
            uint32_t b1 = Bs16[fc + 4][t * 8 + (lane >> 2)];
            mma_f16(c[t], a0, a1, a2, a3, b0, b1);
        }
    }

    // ---- epilogue: bias + mask/gh + relu -> fp16 only ----------------------
    const int m4 = g_mask4;
    #pragma unroll
    for (int half = 0; half < 2; half++) {
        const int r = row0 + wid * 16 + (lane >> 2) + half * 8;
        if (r >= NN) continue;
        bool mb = m4 ? (((const unsigned int*)maskp)[r] != 0u)
                     : (((const unsigned char*)maskp)[r] != 0);
        const float* gr = mb ? nullptr : (gh + (size_t)g2[r] * 128);
        #pragma unroll
        for (int t = 0; t < 16; t++) {
            const int cc = t * 8 + 2 * (lane & 3);
            float v0 = c[t][half * 2 + 0];
            float v1 = c[t][half * 2 + 1];
            float2 bv = *(const float2*)&bias[cc];
            v0 += bv.x; v1 += bv.y;
            if (!mb) {
                float2 gv = *(const float2*)&gr[cc];
                v0 = gv.x; v1 = gv.y;
            }
            v0 = fmaxf(v0, 0.f);
            v1 = fmaxf(v1, 0.f);
            *(uint32_t*)(g_h16 + (size_t)r * 128 + cc) = pack_h2(v0, v1);
        }
    }
}

// ---------------- fp16 layer-3 GEMM: hB16 @ [W3s|W3n] -----------------------
// N=80 (10 tiles). K=128 (8 kb). cols 0..39 -> tS (+b3); 40..79 -> tA.
__global__ void __launch_bounds__(256)
k_gemm_hc3(const float* __restrict__ W3s, const float* __restrict__ W3n,
           const float* __restrict__ b3)
{
    __shared__ uint32_t As16[128][12];
    __shared__ uint32_t Bs16[8][136];

    const int tid  = threadIdx.x;
    const int lane = tid & 31;
    const int wid  = tid >> 5;
    const int row0 = blockIdx.x * 128;

    float c[10][4];
    #pragma unroll
    for (int t = 0; t < 10; t++)
        #pragma unroll
        for (int j = 0; j < 4; j++) c[t][j] = 0.f;

    const int ar = tid >> 1;
    const int aw = (tid & 1) * 4;
    const int bk2 = tid >> 5;
    const int bc  = (tid & 31) * 4;

    #pragma unroll 1
    for (int kb = 0; kb < 8; ++kb) {
        const int kBase = kb * 16;

        uint4 av;
        const int grow = row0 + ar;
        if (grow < NN) {
            av = *(const uint4*)(g_h16 + (size_t)grow * FD + kBase + aw * 2);
        } else {
            av = make_uint4(0u, 0u, 0u, 0u);
        }
        float4 r0, r1;
        {
            const int k0 = kBase + 2 * bk2;
            if (bc < 40) {
                r0 = *(const float4*)(W3s + (size_t)k0 * NC + bc);
                r1 = *(const float4*)(W3s + (size_t)(k0 + 1) * NC + bc);
            } else if (bc < 80) {
                r0 = *(const float4*)(W3n + (size_t)k0 * NC + (bc - 40));
                r1 = *(const float4*)(W3n + (size_t)(k0 + 1) * NC + (bc - 40));
            } else {
                r0 = make_float4(0.f, 0.f, 0.f, 0.f);
                r1 = r0;
            }
        }

        __syncthreads();
        As16[ar][aw + 0] = av.x; As16[ar][aw + 1] = av.y;
        As16[ar][aw + 2] = av.z; As16[ar][aw + 3] = av.w;
        Bs16[bk2][bc + 0] = pack_h2(r0.x, r1.x);
        Bs16[bk2][bc + 1] = pack_h2(r0.y, r1.y);
        Bs16[bk2][bc + 2] = pack_h2(r0.z, r1.z);
        Bs16[bk2][bc + 3] = pack_h2(r0.w, r1.w);
        __syncthreads();

        const int fr = wid * 16 + (lane >> 2);
        const int fc = lane & 3;
        uint32_t a0 = As16[fr][fc];
        uint32_t a1 = As16[fr + 8][fc];
        uint32_t a2 = As16[fr][fc + 4];
        uint32_t a3 = As16[fr + 8][fc + 4];
        #pragma unroll
        for (int t = 0; t < 10; t++) {
            uint32_t b0 = Bs16[fc][t * 8 + (lane >> 2)];
            uint32_t b1 = Bs16[fc + 4][t * 8 + (lane >> 2)];
            mma_f16(c[t], a0, a1, a2, a3, b0, b1);
        }
    }

    #pragma unroll
    for (int half = 0; half < 2; half++) {
        const int r = row0 + wid * 16 + (lane >> 2) + half * 8;
        if (r >= NN) continue;
        #pragma unroll
        for (int t = 0; t < 10; t++) {
            const int cc = t * 8 + 2 * (lane & 3);
            float v0 = c[t][half * 2 + 0];
            float v1 = c[t][half * 2 + 1];
            if (t < 5) {
                float2 bv = *(const float2*)&b3[cc];
                v0 += bv.x; v1 += bv.y;
                float2 o; o.x = v0; o.y = v1;
                *(float2*)&g_tS[(size_t)r * NC + cc] = o;
            } else {
                float2 o; o.x = v0; o.y = v1;
                *(float2*)&g_tA[(size_t)r * NC + (cc - 40)] = o;
            }
        }
    }
}

// ---------------- launch ----------------------------------------------------
extern "C" void kernel_launch(void* const* d_in, const int* in_sizes, int n_in,
                              void* d_out, int out_size)
{
    const float* feat = (const float*)d_in[0];
    const float* gh   = (const float*)d_in[1];
    const float* gh2  = (const float*)d_in[2];
    const float* W1s  = (const float*)d_in[3];
    const float* W1n  = (const float*)d_in[4];
    const float* b1   = (const float*)d_in[5];
    const float* W2s  = (const float*)d_in[6];
    const float* W2n  = (const float*)d_in[7];
    const float* b2   = (const float*)d_in[8];
    const float* W3s  = (const float*)d_in[9];
    const float* W3n  = (const float*)d_in[10];
    const float* b3   = (const float*)d_in[11];
    const int*   esrc = (const int*)d_in[12];
    const int*   edst = (const int*)d_in[13];
    const int*   g2   = (const int*)d_in[14];
    const void*  mask = (const void*)d_in[15];
    float* out = (float*)d_out;

    const int TB = 256;
    const int scanBlocks = (NN + 1023) / 1024;
    const int aggBlocks  = (NN * 32 + TB - 1) / TB;
    const int gemmBlocks = (NN + 127) / 128;

    // CSR build + fp16 convert
    k_setup<<<(NN * FD / 8 + TB - 1) / TB, TB>>>(feat, (const unsigned int*)mask);
    k_hist<<<(NE + TB - 1) / TB, TB>>>(edst);
    k_scanA<<<scanBlocks, 1024>>>();
    k_scanC<<<(NN + TB - 1) / TB, TB>>>(scanBlocks);
    k_scatter<<<(NE + TB - 1) / TB, TB>>>(esrc, edst);

    // Layer 1: agg16(feat16); fp16 GEMM -> hA16 (in place in g_h16)
    k_agg16<<<aggBlocks, TB>>>();
    k_gemm_hc<<<gemmBlocks, TB>>>(W1s, W1n, b1, mask, gh, g2);
    // Layer 2: agg16(hA16); fp16 GEMM -> hB16
    k_agg16<<<aggBlocks, TB>>>();
    k_gemm_hc<<<gemmBlocks, TB>>>(W2s, W2n, b2, mask, gh2, g2);
    // Layer 3: fused fp16 GEMM -> tS, tA; agg40 adds tS and writes out
    k_gemm_hc3<<<gemmBlocks, TB>>>(W3s, W3n, b3);
    k_agg40<<<aggBlocks, TB>>>(out);
}